// round 9
// baseline (speedup 1.0000x reference)
#include <cuda_runtime.h>
#include <cuda_fp16.h>

// B=4, N=256, M=256, D=64. One CTA per (b,i) tile [256 rows, 64 dim].
// Fused algebra (precomputed in a tiny pre-kernel):
//   Wg = (Wk^T Wq)/8, W2 = Wo*Wv, h1 = Wk^T bq/8, h2 = Wq^T bk/8, wbv = Wo bv, s0 = bk.bq/8
//   S = X*Wg*X^T + t2_a + t3_c + s0 ;  P = relu(S) ; U = P*X
//   out = U*inv*W2^T + cden*wbv + bo + x ; LayerNorm.
// 256 threads = 8 warps; warp w owns rows [32w,32w+32) as two m16 tiles.
// mma.sync m16n8k16 f16; B-operands via ldmatrix.x4 (4 MMAs per LDSM).

#define QS 72    // sX row stride (halves)
#define WS 72    // weight row stride (halves)
#define VS 264   // sXt row stride (halves)

__device__ float g_Wg[4096], g_W2[4096], g_h1[64], g_h2[64], g_wbv[64], g_s0;

__global__ void precompute_kernel(const float* __restrict__ Wq, const float* __restrict__ Wk,
                                  const float* __restrict__ Wv, const float* __restrict__ Wo,
                                  const float* __restrict__ bq, const float* __restrict__ bk,
                                  const float* __restrict__ bv)
{
    int i = blockIdx.x * 256 + threadIdx.x;      // 0..4095
    int n = i >> 6, k = i & 63;
    float a = 0.f, b = 0.f;
    for (int j = 0; j < 64; j++) {
        a += Wk[j * 64 + k] * Wq[j * 64 + n];    // g_Wg[n][k] = (Wk^T Wq)[k][n]
        b += Wo[n * 64 + j] * Wv[j * 64 + k];    // g_W2[n][k] = (Wo Wv)[n][k]
    }
    g_Wg[i] = a * 0.125f;
    g_W2[i] = b;
    if (i < 64) {
        float h1 = 0.f, h2 = 0.f, wv = 0.f;
        for (int j = 0; j < 64; j++) {
            h1 += bq[j] * Wk[j * 64 + i];
            h2 += bk[j] * Wq[j * 64 + i];
            wv += Wo[i * 64 + j] * bv[j];
        }
        g_h1[i] = h1 * 0.125f; g_h2[i] = h2 * 0.125f; g_wbv[i] = wv;
    }
    if (i == 0) {
        float s = 0.f;
        for (int j = 0; j < 64; j++) s += bk[j] * bq[j];
        g_s0 = s * 0.125f;
    }
}

__device__ __forceinline__ void mma16(float4& d, const unsigned a[4], unsigned b0, unsigned b1) {
    asm("mma.sync.aligned.m16n8k16.row.col.f32.f16.f16.f32 "
        "{%0,%1,%2,%3},{%4,%5,%6,%7},{%8,%9},{%0,%1,%2,%3};"
        : "+f"(d.x), "+f"(d.y), "+f"(d.z), "+f"(d.w)
        : "r"(a[0]), "r"(a[1]), "r"(a[2]), "r"(a[3]), "r"(b0), "r"(b1));
}

__device__ __forceinline__ void ldsm4(unsigned& r0, unsigned& r1, unsigned& r2, unsigned& r3,
                                      const __half* p) {
    unsigned a = (unsigned)__cvta_generic_to_shared(p);
    asm volatile("ldmatrix.sync.aligned.m8n8.x4.shared.b16 {%0,%1,%2,%3},[%4];"
                 : "=r"(r0), "=r"(r1), "=r"(r2), "=r"(r3) : "r"(a));
}

__device__ __forceinline__ unsigned pack2(float lo, float hi) {
    __half2 h = __floats2half2_rn(lo, hi);
    return *reinterpret_cast<unsigned*>(&h);
}

// Stage a 64x64 fp32 matrix (row-major [n][k]) into an fp16 smem slot.
__device__ __forceinline__ void stageW(const float* __restrict__ W, __half* dst, int tid) {
    const int f  = tid >> 2;
    const int e0 = (tid & 3) * 16;
    const float* src = W + f * 64 + e0;
    unsigned u[8];
    #pragma unroll
    for (int i = 0; i < 4; i++) {
        float4 p = *(const float4*)(src + 4 * i);
        u[2*i]   = pack2(p.x, p.y);
        u[2*i+1] = pack2(p.z, p.w);
    }
    *(uint4*)&dst[f * WS + e0]     = *(uint4*)&u[0];
    *(uint4*)&dst[f * WS + e0 + 8] = *(uint4*)&u[4];
}

__global__ void __launch_bounds__(256)
pair_attn_v7(const float* __restrict__ x_all,
             const float* __restrict__ bo,
             const float* __restrict__ lng, const float* __restrict__ lnb,
             float* __restrict__ out_all)
{
    extern __shared__ __half sm[];
    __half* sX  = sm;                    // [256][QS] X rows fp16
    __half* sXt = sX + 256 * QS;         // [64][VS]  X transposed: sXt[d][c]
    __half* sW  = sXt + 64 * VS;         // [2][64][WS] slot0=Wg, slot1=W2
    float*  t2s = (float*)(sW + 2 * 64 * WS);   // [256] x.h1
    float*  t3s = t2s + 256;                     // [256] x.h2 + s0

    const int tid  = threadIdx.x;
    const int lane = tid & 31;
    const int wrp  = tid >> 5;
    const int g    = lane >> 2;
    const int t    = lane & 3;
    const int R0   = wrp * 32;
    const int lro  = ((lane >> 4) & 1) * 8 + (lane & 7);  // B-operand ldsm lane map
    const int lco  = ((lane >> 3) & 1) * 8;
    const int aro  = lane & 15;                           // A-operand ldsm lane map
    const int aco  = ((lane >> 4) & 1) * 8;

    const float* xg = x_all   + (size_t)blockIdx.x * 16384;
    float*       og = out_all + (size_t)blockIdx.x * 16384;

    // ---- stage X rows (fp16), Xt (fp16, transposed), Wg, W2, t2/t3 ----
    {
        const float4* x4 = (const float4*)xg;
        #pragma unroll
        for (int i = 0; i < 16; i++) {
            int idx = tid + 256 * i;
            int row = idx >> 4, c4 = idx & 15;
            float4 v = x4[idx];
            *(unsigned*)&sX[row * QS + c4 * 4]     = pack2(v.x, v.y);
            *(unsigned*)&sX[row * QS + c4 * 4 + 2] = pack2(v.z, v.w);
            int d = c4 * 4;
            sXt[(d + 0) * VS + row] = __float2half_rn(v.x);
            sXt[(d + 1) * VS + row] = __float2half_rn(v.y);
            sXt[(d + 2) * VS + row] = __float2half_rn(v.z);
            sXt[(d + 3) * VS + row] = __float2half_rn(v.w);
        }
        stageW(g_Wg, sW, tid);
        stageW(g_W2, sW + 64 * WS, tid);
        const float4* xr4 = (const float4*)(xg + tid * 64);
        float a = 0.f, b = 0.f;
        #pragma unroll
        for (int i = 0; i < 16; i++) {
            float4 v = xr4[i];
            a = fmaf(v.x, g_h1[4*i], fmaf(v.y, g_h1[4*i+1], fmaf(v.z, g_h1[4*i+2], fmaf(v.w, g_h1[4*i+3], a))));
            b = fmaf(v.x, g_h2[4*i], fmaf(v.y, g_h2[4*i+1], fmaf(v.z, g_h2[4*i+2], fmaf(v.w, g_h2[4*i+3], b))));
        }
        t2s[tid] = a;
        t3s[tid] = b + g_s0;
    }
    __syncthreads();   // the only CTA-wide barrier

    // ---- G = X * Wg^T-as-B  (D->A layout match keeps G in registers) ----
    unsigned ga[2][4][4];
    {
        unsigned xa[2][4][4];
        #pragma unroll
        for (int mt = 0; mt < 2; mt++)
            #pragma unroll
            for (int kt = 0; kt < 4; kt++)
                ldsm4(xa[mt][kt][0], xa[mt][kt][1], xa[mt][kt][2], xa[mt][kt][3],
                      &sX[(R0 + 16 * mt + aro) * QS + 16 * kt + aco]);
        float4 d0[8], d1[8];
        #pragma unroll
        for (int nt = 0; nt < 8; nt++) {
            d0[nt] = make_float4(0.f, 0.f, 0.f, 0.f);
            d1[nt] = d0[nt];
        }
        #pragma unroll
        for (int kt = 0; kt < 4; kt++)
            #pragma unroll
            for (int j = 0; j < 4; j++) {
                unsigned b0, b1, b2, b3;
                ldsm4(b0, b1, b2, b3, &sW[(16 * j + lro) * WS + 16 * kt + lco]);
                mma16(d0[2*j],   xa[0][kt], b0, b1);
                mma16(d0[2*j+1], xa[0][kt], b2, b3);
                mma16(d1[2*j],   xa[1][kt], b0, b1);
                mma16(d1[2*j+1], xa[1][kt], b2, b3);
            }
        #pragma unroll
        for (int kt = 0; kt < 4; kt++) {
            ga[0][kt][0] = pack2(d0[2*kt].x,   d0[2*kt].y);
            ga[0][kt][1] = pack2(d0[2*kt].z,   d0[2*kt].w);
            ga[0][kt][2] = pack2(d0[2*kt+1].x, d0[2*kt+1].y);
            ga[0][kt][3] = pack2(d0[2*kt+1].z, d0[2*kt+1].w);
            ga[1][kt][0] = pack2(d1[2*kt].x,   d1[2*kt].y);
            ga[1][kt][1] = pack2(d1[2*kt].z,   d1[2*kt].w);
            ga[1][kt][2] = pack2(d1[2*kt+1].x, d1[2*kt+1].y);
            ga[1][kt][3] = pack2(d1[2*kt+1].z, d1[2*kt+1].w);
        }
    }

    // ---- per-lane bias row terms ----
    const float t2A0 = t2s[R0 + g],      t2B0 = t2s[R0 + 8 + g];
    const float t2A1 = t2s[R0 + 16 + g], t2B1 = t2s[R0 + 24 + g];

    // ---- mainloop: S=G*Xc^T -> +bias, relu -> pack -> U += P*Xt ----
    float4 ctx[2][8];
    #pragma unroll
    for (int mt = 0; mt < 2; mt++)
        #pragma unroll
        for (int nt = 0; nt < 8; nt++) ctx[mt][nt] = make_float4(0.f, 0.f, 0.f, 0.f);
    float den[2][2] = {{0.f, 0.f}, {0.f, 0.f}};

    #pragma unroll 2
    for (int cb = 0; cb < 16; cb++) {
        float4 s[2][2];
        s[0][0] = make_float4(0.f, 0.f, 0.f, 0.f);
        s[0][1] = s[0][0]; s[1][0] = s[0][0]; s[1][1] = s[0][0];
        #pragma unroll
        for (int kt = 0; kt < 4; kt++) {
            unsigned q0, q1, q2, q3;
            ldsm4(q0, q1, q2, q3, &sX[(16 * cb + lro) * QS + 16 * kt + lco]);
            mma16(s[0][0], ga[0][kt], q0, q1);
            mma16(s[0][1], ga[0][kt], q2, q3);
            mma16(s[1][0], ga[1][kt], q0, q1);
            mma16(s[1][1], ga[1][kt], q2, q3);
        }
        const float tc0 = t3s[16 * cb + 2 * t],     tc1 = t3s[16 * cb + 2 * t + 1];
        const float tc2 = t3s[16 * cb + 8 + 2 * t], tc3 = t3s[16 * cb + 8 + 2 * t + 1];
        unsigned pa[2][4];
        #pragma unroll
        for (int mt = 0; mt < 2; mt++) {
            const float tA = mt ? t2A1 : t2A0, tB = mt ? t2B1 : t2B0;
            float ex = fmaxf(s[mt][0].x + tA + tc0, 0.f), ey = fmaxf(s[mt][0].y + tA + tc1, 0.f);
            float ez = fmaxf(s[mt][0].z + tB + tc0, 0.f), ew = fmaxf(s[mt][0].w + tB + tc1, 0.f);
            float ox = fmaxf(s[mt][1].x + tA + tc2, 0.f), oy = fmaxf(s[mt][1].y + tA + tc3, 0.f);
            float oz = fmaxf(s[mt][1].z + tB + tc2, 0.f), ow = fmaxf(s[mt][1].w + tB + tc3, 0.f);
            den[mt][0] += (ex + ey) + (ox + oy);
            den[mt][1] += (ez + ew) + (oz + ow);
            pa[mt][0] = pack2(ex, ey); pa[mt][1] = pack2(ez, ew);
            pa[mt][2] = pack2(ox, oy); pa[mt][3] = pack2(oz, ow);
        }
        #pragma unroll
        for (int j = 0; j < 4; j++) {
            unsigned v0, v1, v2, v3;
            ldsm4(v0, v1, v2, v3, &sXt[(16 * j + lro) * VS + 16 * cb + lco]);
            mma16(ctx[0][2*j],   pa[0], v0, v1);
            mma16(ctx[0][2*j+1], pa[0], v2, v3);
            mma16(ctx[1][2*j],   pa[1], v0, v1);
            mma16(ctx[1][2*j+1], pa[1], v2, v3);
        }
    }

    // ---- normalize: inv = 1/(den + 256e-12), cden = den*inv ----
    float inv[2][2], cden[2][2];
    #pragma unroll
    for (int mt = 0; mt < 2; mt++)
        #pragma unroll
        for (int hh = 0; hh < 2; hh++) {
            float d = den[mt][hh];
            d += __shfl_xor_sync(0xffffffffu, d, 1);
            d += __shfl_xor_sync(0xffffffffu, d, 2);
            inv[mt][hh]  = 1.0f / (d + 2.56e-10f);
            cden[mt][hh] = d * inv[mt][hh];
        }
    unsigned cf[2][4][4];
    #pragma unroll
    for (int mt = 0; mt < 2; mt++)
        #pragma unroll
        for (int kt = 0; kt < 4; kt++) {
            cf[mt][kt][0] = pack2(ctx[mt][2*kt].x * inv[mt][0],   ctx[mt][2*kt].y * inv[mt][0]);
            cf[mt][kt][1] = pack2(ctx[mt][2*kt].z * inv[mt][1],   ctx[mt][2*kt].w * inv[mt][1]);
            cf[mt][kt][2] = pack2(ctx[mt][2*kt+1].x * inv[mt][0], ctx[mt][2*kt+1].y * inv[mt][0]);
            cf[mt][kt][3] = pack2(ctx[mt][2*kt+1].z * inv[mt][1], ctx[mt][2*kt+1].w * inv[mt][1]);
        }

    // ---- Y = U' * W2^T (slot 1) ----
    float4 y[2][8];
    #pragma unroll
    for (int mt = 0; mt < 2; mt++)
        #pragma unroll
        for (int nt = 0; nt < 8; nt++) y[mt][nt] = make_float4(0.f, 0.f, 0.f, 0.f);
    #pragma unroll
    for (int kt = 0; kt < 4; kt++)
        #pragma unroll
        for (int j = 0; j < 4; j++) {
            unsigned b0, b1, b2, b3;
            ldsm4(b0, b1, b2, b3, &sW[(64 + 16 * j + lro) * WS + 16 * kt + lco]);
            mma16(y[0][2*j],   cf[0][kt], b0, b1);
            mma16(y[0][2*j+1], cf[0][kt], b2, b3);
            mma16(y[1][2*j],   cf[1][kt], b0, b1);
            mma16(y[1][2*j+1], cf[1][kt], b2, b3);
        }

    // ---- epilogue per m-tile: + cden*wbv + bo + x, LayerNorm, store ----
    #pragma unroll
    for (int mt = 0; mt < 2; mt++) {
        const int rA = R0 + 16 * mt + g, rB = rA + 8;
        const float c0 = cden[mt][0], c1 = cden[mt][1];
        float s0 = 0.f, s1 = 0.f, q0 = 0.f, q1 = 0.f;
        #pragma unroll
        for (int nt = 0; nt < 8; nt++) {
            int c = 8 * nt + 2 * t;
            float2 wv = *(const float2*)&g_wbv[c];
            float2 bb = __ldg((const float2*)&bo[c]);
            float2 x0 = *(const float2*)&xg[rA * 64 + c];
            float2 x1 = *(const float2*)&xg[rB * 64 + c];
            y[mt][nt].x += c0 * wv.x + bb.x + x0.x;
            y[mt][nt].y += c0 * wv.y + bb.y + x0.y;
            y[mt][nt].z += c1 * wv.x + bb.x + x1.x;
            y[mt][nt].w += c1 * wv.y + bb.y + x1.y;
            s0 += y[mt][nt].x + y[mt][nt].y;  q0 += y[mt][nt].x * y[mt][nt].x + y[mt][nt].y * y[mt][nt].y;
            s1 += y[mt][nt].z + y[mt][nt].w;  q1 += y[mt][nt].z * y[mt][nt].z + y[mt][nt].w * y[mt][nt].w;
        }
        s0 += __shfl_xor_sync(0xffffffffu, s0, 1); s0 += __shfl_xor_sync(0xffffffffu, s0, 2);
        q0 += __shfl_xor_sync(0xffffffffu, q0, 1); q0 += __shfl_xor_sync(0xffffffffu, q0, 2);
        s1 += __shfl_xor_sync(0xffffffffu, s1, 1); s1 += __shfl_xor_sync(0xffffffffu, s1, 2);
        q1 += __shfl_xor_sync(0xffffffffu, q1, 1); q1 += __shfl_xor_sync(0xffffffffu, q1, 2);
        float mu0 = s0 * (1.f / 64.f), mu1 = s1 * (1.f / 64.f);
        float rs0 = rsqrtf(q0 * (1.f / 64.f) - mu0 * mu0 + 1e-5f);
        float rs1 = rsqrtf(q1 * (1.f / 64.f) - mu1 * mu1 + 1e-5f);
        #pragma unroll
        for (int nt = 0; nt < 8; nt++) {
            int c = 8 * nt + 2 * t;
            float2 gg = __ldg((const float2*)&lng[c]);
            float2 bb = __ldg((const float2*)&lnb[c]);
            *(float2*)&og[rA * 64 + c] = make_float2((y[mt][nt].x - mu0) * rs0 * gg.x + bb.x,
                                                     (y[mt][nt].y - mu0) * rs0 * gg.y + bb.y);
            *(float2*)&og[rB * 64 + c] = make_float2((y[mt][nt].z - mu1) * rs1 * gg.x + bb.x,
                                                     (y[mt][nt].w - mu1) * rs1 * gg.y + bb.y);
        }
    }
}

extern "C" void kernel_launch(void* const* d_in, const int* in_sizes, int n_in,
                              void* d_out, int out_size)
{
    const float* x   = (const float*)d_in[1];
    const float* Wq  = (const float*)d_in[2];
    const float* bq  = (const float*)d_in[3];
    const float* Wk  = (const float*)d_in[4];
    const float* bk  = (const float*)d_in[5];
    const float* Wv  = (const float*)d_in[6];
    const float* bv  = (const float*)d_in[7];
    const float* Wo  = (const float*)d_in[8];
    const float* bo  = (const float*)d_in[9];
    const float* lng = (const float*)d_in[10];
    const float* lnb = (const float*)d_in[11];
    float* out = (float*)d_out;

    int tiles = in_sizes[1] / (256 * 64);   // B*N = 1024

    precompute_kernel<<<16, 256>>>(Wq, Wk, Wv, Wo, bq, bk, bv);

    // smem: (256*QS + 64*VS + 2*64*WS) halves + 512 floats = 89088 + 2048 = 91136 B
    size_t smem = (size_t)(256 * QS + 64 * VS + 2 * 64 * WS) * sizeof(__half) + 512 * sizeof(float);
    cudaFuncSetAttribute(pair_attn_v7,
                         cudaFuncAttributeMaxDynamicSharedMemorySize, (int)smem);

    pair_attn_v7<<<tiles, 256, smem>>>(x, bo, lng, lnb, out);
}

// round 10
// speedup vs baseline: 1.0285x; 1.0285x over previous
#include <cuda_runtime.h>
#include <cuda_fp16.h>

// B=4, N=256, M=256, D=64. One CTA per (b,i) tile [256 rows, 64 dim].
// Precomputed algebra (separate tiny kernel, amortized over 1024 tiles):
//   Wg[n][k] = (Wk^T Wq)[k][n]/8 ; W2[n][k] = (Wo Wv)[n][k]
//   h1 = Wk^T bq/8 ; h2 = Wq^T bk/8 ; wbv = Wo bv ; s0 = bk.bq/8
// Per tile: G = X*Wg ; S = G*X^T + t2_a + t3_c + s0 ; P = relu(S)
//           U = P*X ; out = U*inv*W2^T + cden*wbv + bo + x ; LayerNorm.
// 256 threads = 8 warps; warp w owns rows [32w,32w+32) as two m16 tiles.
// mma.sync m16n8k16 f16; B-operands via ldmatrix.x4 (4 MMAs per LDSM).

#define QS 72    // sX row stride (halves)
#define WS 72    // weight row stride (halves)
#define VS 264   // sXt row stride (halves)

__device__ float g_Wg[4096], g_W2[4096], g_h1[64], g_h2[64], g_wbv[64], g_s0;

__global__ void precompute_kernel(const float* __restrict__ Wq, const float* __restrict__ Wk,
                                  const float* __restrict__ Wv, const float* __restrict__ Wo,
                                  const float* __restrict__ bq, const float* __restrict__ bk,
                                  const float* __restrict__ bv)
{
    int i = blockIdx.x * 128 + threadIdx.x;      // 0..4095
    int n = i >> 6, k = i & 63;
    float a = 0.f, b = 0.f;
    for (int j = 0; j < 64; j++) {
        a += Wk[j * 64 + k] * Wq[j * 64 + n];    // g_Wg[n][k] = (Wk^T Wq)[k][n]
        b += Wo[n * 64 + j] * Wv[j * 64 + k];    // g_W2[n][k] = (Wo Wv)[n][k]
    }
    g_Wg[i] = a * 0.125f;
    g_W2[i] = b;
    if (i < 64) {
        float h1 = 0.f, h2 = 0.f, wv = 0.f;
        for (int j = 0; j < 64; j++) {
            h1 += bq[j] * Wk[j * 64 + i];
            h2 += bk[j] * Wq[j * 64 + i];
            wv += Wo[i * 64 + j] * bv[j];
        }
        g_h1[i] = h1 * 0.125f; g_h2[i] = h2 * 0.125f; g_wbv[i] = wv;
    }
    if (i == 0) {
        float s = 0.f;
        for (int j = 0; j < 64; j++) s += bk[j] * bq[j];
        g_s0 = s * 0.125f;
    }
}

__device__ __forceinline__ void mma16(float4& d, const unsigned a[4], unsigned b0, unsigned b1) {
    asm("mma.sync.aligned.m16n8k16.row.col.f32.f16.f16.f32 "
        "{%0,%1,%2,%3},{%4,%5,%6,%7},{%8,%9},{%0,%1,%2,%3};"
        : "+f"(d.x), "+f"(d.y), "+f"(d.z), "+f"(d.w)
        : "r"(a[0]), "r"(a[1]), "r"(a[2]), "r"(a[3]), "r"(b0), "r"(b1));
}

__device__ __forceinline__ void ldsm4(unsigned& r0, unsigned& r1, unsigned& r2, unsigned& r3,
                                      const __half* p) {
    unsigned a = (unsigned)__cvta_generic_to_shared(p);
    asm volatile("ldmatrix.sync.aligned.m8n8.x4.shared.b16 {%0,%1,%2,%3},[%4];"
                 : "=r"(r0), "=r"(r1), "=r"(r2), "=r"(r3) : "r"(a));
}

__device__ __forceinline__ unsigned pack2(float lo, float hi) {
    __half2 h = __floats2half2_rn(lo, hi);
    return *reinterpret_cast<unsigned*>(&h);
}

// Stage a 64x64 fp32 matrix (row-major [n][k]) into an fp16 smem slot.
__device__ __forceinline__ void stageW(const float* __restrict__ W, __half* dst, int tid) {
    const int f  = tid >> 2;
    const int e0 = (tid & 3) * 16;
    const float* src = W + f * 64 + e0;
    unsigned u[8];
    #pragma unroll
    for (int i = 0; i < 4; i++) {
        float4 p = *(const float4*)(src + 4 * i);
        u[2*i]   = pack2(p.x, p.y);
        u[2*i+1] = pack2(p.z, p.w);
    }
    *(uint4*)&dst[f * WS + e0]     = *(uint4*)&u[0];
    *(uint4*)&dst[f * WS + e0 + 8] = *(uint4*)&u[4];
}

__global__ void __launch_bounds__(256, 1)
pair_attn_v8(const float* __restrict__ x_all,
             const float* __restrict__ bo,
             const float* __restrict__ lng, const float* __restrict__ lnb,
             float* __restrict__ out_all)
{
    extern __shared__ __half sm[];
    __half* sX  = sm;                    // [256][QS] X rows fp16
    __half* sXt = sX + 256 * QS;         // [64][VS]  X transposed: sXt[d][c]
    __half* sW  = sXt + 64 * VS;         // [2][64][WS] slot0=Wg, slot1=W2
    float*  t2s = (float*)(sW + 2 * 64 * WS);   // [256] x.h1
    float*  t3s = t2s + 256;                     // [256] x.h2 + s0

    const int tid  = threadIdx.x;
    const int lane = tid & 31;
    const int wrp  = tid >> 5;
    const int g    = lane >> 2;
    const int t    = lane & 3;
    const int R0   = wrp * 32;
    const int lro  = ((lane >> 4) & 1) * 8 + (lane & 7);  // B-operand ldsm lane map
    const int lco  = ((lane >> 3) & 1) * 8;

    const float* xg = x_all   + (size_t)blockIdx.x * 16384;
    float*       og = out_all + (size_t)blockIdx.x * 16384;

    // ---- stage X rows (fp16), Xt (fp16 transposed), Wg, W2, and t2/t3 dots ----
    {
        const float4* x4 = (const float4*)xg;
        #pragma unroll
        for (int i = 0; i < 16; i++) {
            int idx = tid + 256 * i;
            int row = idx >> 4, c4 = idx & 15;
            float4 v = x4[idx];
            *(unsigned*)&sX[row * QS + c4 * 4]     = pack2(v.x, v.y);
            *(unsigned*)&sX[row * QS + c4 * 4 + 2] = pack2(v.z, v.w);
            int d = c4 * 4;
            sXt[(d + 0) * VS + row] = __float2half_rn(v.x);
            sXt[(d + 1) * VS + row] = __float2half_rn(v.y);
            sXt[(d + 2) * VS + row] = __float2half_rn(v.z);
            sXt[(d + 3) * VS + row] = __float2half_rn(v.w);
        }
        stageW(g_Wg, sW, tid);
        stageW(g_W2, sW + 64 * WS, tid);
        const float4* xr4 = (const float4*)(xg + tid * 64);
        float a = 0.f, b = 0.f;
        #pragma unroll
        for (int i = 0; i < 16; i++) {
            float4 v = xr4[i];
            a = fmaf(v.x, g_h1[4*i], fmaf(v.y, g_h1[4*i+1], fmaf(v.z, g_h1[4*i+2], fmaf(v.w, g_h1[4*i+3], a))));
            b = fmaf(v.x, g_h2[4*i], fmaf(v.y, g_h2[4*i+1], fmaf(v.z, g_h2[4*i+2], fmaf(v.w, g_h2[4*i+3], b))));
        }
        t2s[tid] = a;
        t3s[tid] = b + g_s0;
    }
    __syncthreads();   // the only CTA-wide barrier

    // ---- G = X * Wg (A-frags from gmem, round-4 style; D->A keeps G in regs) ----
    unsigned ga[2][4][4];
    {
        unsigned xa[2][4][4];
        #pragma unroll
        for (int mt = 0; mt < 2; mt++) {
            const int rA = R0 + 16 * mt + g, rB = rA + 8;
            #pragma unroll
            for (int kt = 0; kt < 4; kt++) {
                int c = 16 * kt + 2 * t;
                float2 v0 = *(const float2*)&xg[rA * 64 + c];
                float2 v1 = *(const float2*)&xg[rB * 64 + c];
                float2 v2 = *(const float2*)&xg[rA * 64 + c + 8];
                float2 v3 = *(const float2*)&xg[rB * 64 + c + 8];
                xa[mt][kt][0] = pack2(v0.x, v0.y);
                xa[mt][kt][1] = pack2(v1.x, v1.y);
                xa[mt][kt][2] = pack2(v2.x, v2.y);
                xa[mt][kt][3] = pack2(v3.x, v3.y);
            }
        }
        float4 d0[8], d1[8];
        #pragma unroll
        for (int nt = 0; nt < 8; nt++) {
            d0[nt] = make_float4(0.f, 0.f, 0.f, 0.f);
            d1[nt] = d0[nt];
        }
        #pragma unroll
        for (int kt = 0; kt < 4; kt++)
            #pragma unroll
            for (int j = 0; j < 4; j++) {
                unsigned b0, b1, b2, b3;
                ldsm4(b0, b1, b2, b3, &sW[(16 * j + lro) * WS + 16 * kt + lco]);
                mma16(d0[2*j],   xa[0][kt], b0, b1);
                mma16(d0[2*j+1], xa[0][kt], b2, b3);
                mma16(d1[2*j],   xa[1][kt], b0, b1);
                mma16(d1[2*j+1], xa[1][kt], b2, b3);
            }
        #pragma unroll
        for (int kt = 0; kt < 4; kt++) {
            ga[0][kt][0] = pack2(d0[2*kt].x,   d0[2*kt].y);
            ga[0][kt][1] = pack2(d0[2*kt].z,   d0[2*kt].w);
            ga[0][kt][2] = pack2(d0[2*kt+1].x, d0[2*kt+1].y);
            ga[0][kt][3] = pack2(d0[2*kt+1].z, d0[2*kt+1].w);
            ga[1][kt][0] = pack2(d1[2*kt].x,   d1[2*kt].y);
            ga[1][kt][1] = pack2(d1[2*kt].z,   d1[2*kt].w);
            ga[1][kt][2] = pack2(d1[2*kt+1].x, d1[2*kt+1].y);
            ga[1][kt][3] = pack2(d1[2*kt+1].z, d1[2*kt+1].w);
        }
    }

    // ---- per-lane row bias terms ----
    const float t2A0 = t2s[R0 + g],      t2B0 = t2s[R0 + 8 + g];
    const float t2A1 = t2s[R0 + 16 + g], t2B1 = t2s[R0 + 24 + g];

    // ---- mainloop: S = G*X^T -> +bias, relu -> pack -> U += P*Xt ----
    float4 ctx[2][8];
    #pragma unroll
    for (int mt = 0; mt < 2; mt++)
        #pragma unroll
        for (int nt = 0; nt < 8; nt++) ctx[mt][nt] = make_float4(0.f, 0.f, 0.f, 0.f);
    float den[2][2] = {{0.f, 0.f}, {0.f, 0.f}};

    #pragma unroll 2
    for (int cb = 0; cb < 16; cb++) {
        // hoisted column bias terms (off the MMA->relu critical path)
        const float tc0 = t3s[16 * cb + 2 * t],     tc1 = t3s[16 * cb + 2 * t + 1];
        const float tc2 = t3s[16 * cb + 8 + 2 * t], tc3 = t3s[16 * cb + 8 + 2 * t + 1];
        float4 s[2][2];
        s[0][0] = make_float4(0.f, 0.f, 0.f, 0.f);
        s[0][1] = s[0][0]; s[1][0] = s[0][0]; s[1][1] = s[0][0];
        #pragma unroll
        for (int kt = 0; kt < 4; kt++) {
            unsigned q0, q1, q2, q3;
            ldsm4(q0, q1, q2, q3, &sX[(16 * cb + lro) * QS + 16 * kt + lco]);
            mma16(s[0][0], ga[0][kt], q0, q1);
            mma16(s[0][1], ga[0][kt], q2, q3);
            mma16(s[1][0], ga[1][kt], q0, q1);
            mma16(s[1][1], ga[1][kt], q2, q3);
        }
        unsigned pa[2][4];
        #pragma unroll
        for (int mt = 0; mt < 2; mt++) {
            const float tA = mt ? t2A1 : t2A0, tB = mt ? t2B1 : t2B0;
            float ex = fmaxf(s[mt][0].x + tA + tc0, 0.f), ey = fmaxf(s[mt][0].y + tA + tc1, 0.f);
            float ez = fmaxf(s[mt][0].z + tB + tc0, 0.f), ew = fmaxf(s[mt][0].w + tB + tc1, 0.f);
            float ox = fmaxf(s[mt][1].x + tA + tc2, 0.f), oy = fmaxf(s[mt][1].y + tA + tc3, 0.f);
            float oz = fmaxf(s[mt][1].z + tB + tc2, 0.f), ow = fmaxf(s[mt][1].w + tB + tc3, 0.f);
            den[mt][0] += (ex + ey) + (ox + oy);
            den[mt][1] += (ez + ew) + (oz + ow);
            pa[mt][0] = pack2(ex, ey); pa[mt][1] = pack2(ez, ew);
            pa[mt][2] = pack2(ox, oy); pa[mt][3] = pack2(oz, ow);
        }
        #pragma unroll
        for (int j = 0; j < 4; j++) {
            unsigned v0, v1, v2, v3;
            ldsm4(v0, v1, v2, v3, &sXt[(16 * j + lro) * VS + 16 * cb + lco]);
            mma16(ctx[0][2*j],   pa[0], v0, v1);
            mma16(ctx[0][2*j+1], pa[0], v2, v3);
            mma16(ctx[1][2*j],   pa[1], v0, v1);
            mma16(ctx[1][2*j+1], pa[1], v2, v3);
        }
    }

    // ---- normalize: inv = 1/(den + 256e-12), cden = den*inv ----
    float inv[2][2], cden[2][2];
    #pragma unroll
    for (int mt = 0; mt < 2; mt++)
        #pragma unroll
        for (int hh = 0; hh < 2; hh++) {
            float d = den[mt][hh];
            d += __shfl_xor_sync(0xffffffffu, d, 1);
            d += __shfl_xor_sync(0xffffffffu, d, 2);
            inv[mt][hh]  = 1.0f / (d + 2.56e-10f);
            cden[mt][hh] = d * inv[mt][hh];
        }
    unsigned cf[2][4][4];
    #pragma unroll
    for (int mt = 0; mt < 2; mt++)
        #pragma unroll
        for (int kt = 0; kt < 4; kt++) {
            cf[mt][kt][0] = pack2(ctx[mt][2*kt].x * inv[mt][0],   ctx[mt][2*kt].y * inv[mt][0]);
            cf[mt][kt][1] = pack2(ctx[mt][2*kt].z * inv[mt][1],   ctx[mt][2*kt].w * inv[mt][1]);
            cf[mt][kt][2] = pack2(ctx[mt][2*kt+1].x * inv[mt][0], ctx[mt][2*kt+1].y * inv[mt][0]);
            cf[mt][kt][3] = pack2(ctx[mt][2*kt+1].z * inv[mt][1], ctx[mt][2*kt+1].w * inv[mt][1]);
        }

    // ---- Y = U' * W2^T (slot 1) ----
    float4 y[2][8];
    #pragma unroll
    for (int mt = 0; mt < 2; mt++)
        #pragma unroll
        for (int nt = 0; nt < 8; nt++) y[mt][nt] = make_float4(0.f, 0.f, 0.f, 0.f);
    #pragma unroll
    for (int kt = 0; kt < 4; kt++)
        #pragma unroll
        for (int j = 0; j < 4; j++) {
            unsigned b0, b1, b2, b3;
            ldsm4(b0, b1, b2, b3, &sW[(64 + 16 * j + lro) * WS + 16 * kt + lco]);
            mma16(y[0][2*j],   cf[0][kt], b0, b1);
            mma16(y[0][2*j+1], cf[0][kt], b2, b3);
            mma16(y[1][2*j],   cf[1][kt], b0, b1);
            mma16(y[1][2*j+1], cf[1][kt], b2, b3);
        }

    // ---- epilogue per m-tile: + cden*wbv + bo + x, LayerNorm, store ----
    #pragma unroll
    for (int mt = 0; mt < 2; mt++) {
        const int rA = R0 + 16 * mt + g, rB = rA + 8;
        const float c0 = cden[mt][0], c1 = cden[mt][1];
        float s0 = 0.f, s1 = 0.f, q0 = 0.f, q1 = 0.f;
        #pragma unroll
        for (int nt = 0; nt < 8; nt++) {
            int c = 8 * nt + 2 * t;
            float2 wv = *(const float2*)&g_wbv[c];
            float2 bb = __ldg((const float2*)&bo[c]);
            float2 x0 = *(const float2*)&xg[rA * 64 + c];
            float2 x1 = *(const float2*)&xg[rB * 64 + c];
            y[mt][nt].x += c0 * wv.x + bb.x + x0.x;
            y[mt][nt].y += c0 * wv.y + bb.y + x0.y;
            y[mt][nt].z += c1 * wv.x + bb.x + x1.x;
            y[mt][nt].w += c1 * wv.y + bb.y + x1.y;
            s0 += y[mt][nt].x + y[mt][nt].y;  q0 += y[mt][nt].x * y[mt][nt].x + y[mt][nt].y * y[mt][nt].y;
            s1 += y[mt][nt].z + y[mt][nt].w;  q1 += y[mt][nt].z * y[mt][nt].z + y[mt][nt].w * y[mt][nt].w;
        }
        s0 += __shfl_xor_sync(0xffffffffu, s0, 1); s0 += __shfl_xor_sync(0xffffffffu, s0, 2);
        q0 += __shfl_xor_sync(0xffffffffu, q0, 1); q0 += __shfl_xor_sync(0xffffffffu, q0, 2);
        s1 += __shfl_xor_sync(0xffffffffu, s1, 1); s1 += __shfl_xor_sync(0xffffffffu, s1, 2);
        q1 += __shfl_xor_sync(0xffffffffu, q1, 1); q1 += __shfl_xor_sync(0xffffffffu, q1, 2);
        float mu0 = s0 * (1.f / 64.f), mu1 = s1 * (1.f / 64.f);
        float rs0 = rsqrtf(q0 * (1.f / 64.f) - mu0 * mu0 + 1e-5f);
        float rs1 = rsqrtf(q1 * (1.f / 64.f) - mu1 * mu1 + 1e-5f);
        #pragma unroll
        for (int nt = 0; nt < 8; nt++) {
            int c = 8 * nt + 2 * t;
            float2 gg = __ldg((const float2*)&lng[c]);
            float2 bb = __ldg((const float2*)&lnb[c]);
            *(float2*)&og[rA * 64 + c] = make_float2((y[mt][nt].x - mu0) * rs0 * gg.x + bb.x,
                                                     (y[mt][nt].y - mu0) * rs0 * gg.y + bb.y);
            *(float2*)&og[rB * 64 + c] = make_float2((y[mt][nt].z - mu1) * rs1 * gg.x + bb.x,
                                                     (y[mt][nt].w - mu1) * rs1 * gg.y + bb.y);
        }
    }
}

extern "C" void kernel_launch(void* const* d_in, const int* in_sizes, int n_in,
                              void* d_out, int out_size)
{
    const float* x   = (const float*)d_in[1];
    const float* Wq  = (const float*)d_in[2];
    const float* bq  = (const float*)d_in[3];
    const float* Wk  = (const float*)d_in[4];
    const float* bk  = (const float*)d_in[5];
    const float* Wv  = (const float*)d_in[6];
    const float* bv  = (const float*)d_in[7];
    const float* Wo  = (const float*)d_in[8];
    const float* bo  = (const float*)d_in[9];
    const float* lng = (const float*)d_in[10];
    const float* lnb = (const float*)d_in[11];
    float* out = (float*)d_out;

    int tiles = in_sizes[1] / (256 * 64);   // B*N = 1024

    precompute_kernel<<<32, 128>>>(Wq, Wk, Wv, Wo, bq, bk, bv);

    // smem: (256*QS + 64*VS + 2*64*WS) halves + 512 floats = 89088 + 2048 = 91136 B
    size_t smem = (size_t)(256 * QS + 64 * VS + 2 * 64 * WS) * sizeof(__half) + 512 * sizeof(float);
    cudaFuncSetAttribute(pair_attn_v8,
                         cudaFuncAttributeMaxDynamicSharedMemorySize, (int)smem);

    pair_attn_v8<<<tiles, 256, smem>>>(x, bo, lng, lnb, out);
}

// round 11
// speedup vs baseline: 1.2204x; 1.1866x over previous
#include <cuda_runtime.h>
#include <cuda_fp16.h>

// B=4, N=256, M=256, D=64. One CTA per (b,i) tile [256 rows, 64 dim].
// Fused algebra: Wg[n][k]=(Wk^T Wq)[k][n]/8, W2[n][k]=(Wo Wv)[n][k],
//   h1=Wk^T bq/8, h2=Wq^T bk/8, wbv=Wo bv, s0=bk.bq/8.
// Per tile: G=X*Wg ; S=G*X^T + t2_a + t3_c ; P=relu(S) ; U=P*X ;
//   out = U*inv*W2^T + cden*wbv + bo + x ; LayerNorm.
// U-GEMM B-operand comes from ldmatrix.x4.TRANS on row-major sX (no sXt copy).
// 256 threads = 8 warps; warp w owns rows [32w,32w+32) (4 MMAs per LDSM).

#define QS 72    // sX row stride (halves)
#define WS 72    // weight row stride (halves)

__device__ float g_Wg[4096], g_W2[4096], g_h1[64], g_h2[64], g_wbv[64], g_s0;

// grid(2): block 0 -> Wg + h1,h2,s0 ; block 1 -> W2 + wbv. smem-staged weights.
__global__ void precompute_kernel(const float* __restrict__ Wq, const float* __restrict__ Wk,
                                  const float* __restrict__ Wv, const float* __restrict__ Wo,
                                  const float* __restrict__ bq, const float* __restrict__ bk,
                                  const float* __restrict__ bv)
{
    __shared__ float sA[4096], sB[4096];
    const int tid = threadIdx.x;
    const float* A = (blockIdx.x == 0) ? Wk : Wv;   // k-indexed operand: sA[j][k]
    const float* Bm = (blockIdx.x == 0) ? Wq : Wo;  // n-indexed operand
    for (int i = tid; i < 1024; i += 256) {
        ((float4*)sA)[i] = ((const float4*)A)[i];
        ((float4*)sB)[i] = ((const float4*)Bm)[i];
    }
    __syncthreads();
    const int n = tid >> 2, k0 = (tid & 3) * 16;
    float acc[16];
    #pragma unroll
    for (int q = 0; q < 16; q++) acc[q] = 0.f;
    if (blockIdx.x == 0) {
        // Wg[n][k] = sum_j Wk[j][k] * Wq[j][n] / 8
        for (int j = 0; j < 64; j++) {
            float wn = sB[j * 64 + n];
            #pragma unroll
            for (int q4 = 0; q4 < 4; q4++) {
                float4 v = *(const float4*)&sA[j * 64 + k0 + 4 * q4];
                acc[4*q4+0] = fmaf(wn, v.x, acc[4*q4+0]);
                acc[4*q4+1] = fmaf(wn, v.y, acc[4*q4+1]);
                acc[4*q4+2] = fmaf(wn, v.z, acc[4*q4+2]);
                acc[4*q4+3] = fmaf(wn, v.w, acc[4*q4+3]);
            }
        }
        #pragma unroll
        for (int q = 0; q < 16; q++) g_Wg[n * 64 + k0 + q] = acc[q] * 0.125f;
        if (tid < 64) {
            float h1 = 0.f, h2 = 0.f;
            for (int j = 0; j < 64; j++) {
                h1 += bq[j] * sA[j * 64 + tid];   // Wk
                h2 += bk[j] * sB[j * 64 + tid];   // Wq
            }
            g_h1[tid] = h1 * 0.125f; g_h2[tid] = h2 * 0.125f;
        }
        if (tid == 0) {
            float s = 0.f;
            for (int j = 0; j < 64; j++) s += bk[j] * bq[j];
            g_s0 = s * 0.125f;
        }
    } else {
        // W2[n][k] = sum_j Wo[n][j] * Wv[j][k]
        for (int j = 0; j < 64; j++) {
            float wn = sB[n * 64 + j];
            #pragma unroll
            for (int q4 = 0; q4 < 4; q4++) {
                float4 v = *(const float4*)&sA[j * 64 + k0 + 4 * q4];
                acc[4*q4+0] = fmaf(wn, v.x, acc[4*q4+0]);
                acc[4*q4+1] = fmaf(wn, v.y, acc[4*q4+1]);
                acc[4*q4+2] = fmaf(wn, v.z, acc[4*q4+2]);
                acc[4*q4+3] = fmaf(wn, v.w, acc[4*q4+3]);
            }
        }
        #pragma unroll
        for (int q = 0; q < 16; q++) g_W2[n * 64 + k0 + q] = acc[q];
        if (tid < 64) {
            float wv = 0.f;
            for (int j = 0; j < 64; j++) wv += sB[tid * 64 + j] * bv[j];  // Wo
            g_wbv[tid] = wv;
        }
    }
}

__device__ __forceinline__ void mma16(float4& d, const unsigned a[4], unsigned b0, unsigned b1) {
    asm("mma.sync.aligned.m16n8k16.row.col.f32.f16.f16.f32 "
        "{%0,%1,%2,%3},{%4,%5,%6,%7},{%8,%9},{%0,%1,%2,%3};"
        : "+f"(d.x), "+f"(d.y), "+f"(d.z), "+f"(d.w)
        : "r"(a[0]), "r"(a[1]), "r"(a[2]), "r"(a[3]), "r"(b0), "r"(b1));
}

__device__ __forceinline__ void ldsm4(unsigned& r0, unsigned& r1, unsigned& r2, unsigned& r3,
                                      const __half* p) {
    unsigned a = (unsigned)__cvta_generic_to_shared(p);
    asm volatile("ldmatrix.sync.aligned.m8n8.x4.shared.b16 {%0,%1,%2,%3},[%4];"
                 : "=r"(r0), "=r"(r1), "=r"(r2), "=r"(r3) : "r"(a));
}

__device__ __forceinline__ void ldsm4t(unsigned& r0, unsigned& r1, unsigned& r2, unsigned& r3,
                                       const __half* p) {
    unsigned a = (unsigned)__cvta_generic_to_shared(p);
    asm volatile("ldmatrix.sync.aligned.m8n8.x4.trans.shared.b16 {%0,%1,%2,%3},[%4];"
                 : "=r"(r0), "=r"(r1), "=r"(r2), "=r"(r3) : "r"(a));
}

__device__ __forceinline__ unsigned pack2(float lo, float hi) {
    __half2 h = __floats2half2_rn(lo, hi);
    return *reinterpret_cast<unsigned*>(&h);
}

__device__ __forceinline__ void stageW(const float* __restrict__ W, __half* dst, int tid) {
    const int f  = tid >> 2;
    const int e0 = (tid & 3) * 16;
    const float* src = W + f * 64 + e0;
    unsigned u[8];
    #pragma unroll
    for (int i = 0; i < 4; i++) {
        float4 p = *(const float4*)(src + 4 * i);
        u[2*i]   = pack2(p.x, p.y);
        u[2*i+1] = pack2(p.z, p.w);
    }
    *(uint4*)&dst[f * WS + e0]     = *(uint4*)&u[0];
    *(uint4*)&dst[f * WS + e0 + 8] = *(uint4*)&u[4];
}

__global__ void __launch_bounds__(256, 1)
pair_attn_v9(const float* __restrict__ x_all,
             const float* __restrict__ bo,
             const float* __restrict__ lng, const float* __restrict__ lnb,
             float* __restrict__ out_all)
{
    extern __shared__ __half sm[];
    __half* sX  = sm;                    // [256][QS] X rows fp16
    __half* sW  = sX + 256 * QS;         // [2][64][WS] slot0=Wg, slot1=W2
    float*  t2s = (float*)(sW + 2 * 64 * WS);   // [256] x.h1
    float*  t3s = t2s + 256;                     // [256] x.h2 + s0

    const int tid  = threadIdx.x;
    const int lane = tid & 31;
    const int wrp  = tid >> 5;
    const int g    = lane >> 2;
    const int t    = lane & 3;
    const int R0   = wrp * 32;
    const int lro  = ((lane >> 4) & 1) * 8 + (lane & 7);  // B-operand non-trans map
    const int lco  = ((lane >> 3) & 1) * 8;
    const int vro  = ((lane >> 3) & 1) * 8 + (lane & 7);  // B-operand TRANS map (bits swapped)
    const int vco  = ((lane >> 4) & 1) * 8;
    const int aro  = lane & 15;                           // A-operand map
    const int aco  = ((lane >> 4) & 1) * 8;

    const float* xg = x_all   + (size_t)blockIdx.x * 16384;
    float*       og = out_all + (size_t)blockIdx.x * 16384;

    // ---- stage X rows (fp16, vectorized, ~2-way max), weights, t2/t3 dots ----
    {
        const float4* x4 = (const float4*)xg;
        #pragma unroll
        for (int i = 0; i < 16; i++) {
            int idx = tid + 256 * i;
            int row = idx >> 4, c4 = idx & 15;
            float4 v = x4[idx];
            *(uint2*)&sX[row * QS + c4 * 4] = make_uint2(pack2(v.x, v.y), pack2(v.z, v.w));
        }
        stageW(g_Wg, sW, tid);
        stageW(g_W2, sW + 64 * WS, tid);
        const float4* xr4 = (const float4*)(xg + tid * 64);
        float a = 0.f, b = 0.f;
        #pragma unroll
        for (int i = 0; i < 16; i++) {
            float4 v = xr4[i];
            a = fmaf(v.x, g_h1[4*i], fmaf(v.y, g_h1[4*i+1], fmaf(v.z, g_h1[4*i+2], fmaf(v.w, g_h1[4*i+3], a))));
            b = fmaf(v.x, g_h2[4*i], fmaf(v.y, g_h2[4*i+1], fmaf(v.z, g_h2[4*i+2], fmaf(v.w, g_h2[4*i+3], b))));
        }
        t2s[tid] = a;
        t3s[tid] = b + g_s0;
    }
    __syncthreads();   // the only CTA-wide barrier

    // ---- G = X * Wg (A-frags via ldmatrix; D->A layout keeps G in registers) ----
    unsigned ga[2][4][4];
    {
        unsigned xa[2][4][4];
        #pragma unroll
        for (int mt = 0; mt < 2; mt++)
            #pragma unroll
            for (int kt = 0; kt < 4; kt++)
                ldsm4(xa[mt][kt][0], xa[mt][kt][1], xa[mt][kt][2], xa[mt][kt][3],
                      &sX[(R0 + 16 * mt + aro) * QS + 16 * kt + aco]);
        float4 d0[8], d1[8];
        #pragma unroll
        for (int nt = 0; nt < 8; nt++) {
            d0[nt] = make_float4(0.f, 0.f, 0.f, 0.f);
            d1[nt] = d0[nt];
        }
        #pragma unroll
        for (int kt = 0; kt < 4; kt++)
            #pragma unroll
            for (int j = 0; j < 4; j++) {
                unsigned b0, b1, b2, b3;
                ldsm4(b0, b1, b2, b3, &sW[(16 * j + lro) * WS + 16 * kt + lco]);
                mma16(d0[2*j],   xa[0][kt], b0, b1);
                mma16(d0[2*j+1], xa[0][kt], b2, b3);
                mma16(d1[2*j],   xa[1][kt], b0, b1);
                mma16(d1[2*j+1], xa[1][kt], b2, b3);
            }
        #pragma unroll
        for (int kt = 0; kt < 4; kt++) {
            ga[0][kt][0] = pack2(d0[2*kt].x,   d0[2*kt].y);
            ga[0][kt][1] = pack2(d0[2*kt].z,   d0[2*kt].w);
            ga[0][kt][2] = pack2(d0[2*kt+1].x, d0[2*kt+1].y);
            ga[0][kt][3] = pack2(d0[2*kt+1].z, d0[2*kt+1].w);
            ga[1][kt][0] = pack2(d1[2*kt].x,   d1[2*kt].y);
            ga[1][kt][1] = pack2(d1[2*kt].z,   d1[2*kt].w);
            ga[1][kt][2] = pack2(d1[2*kt+1].x, d1[2*kt+1].y);
            ga[1][kt][3] = pack2(d1[2*kt+1].z, d1[2*kt+1].w);
        }
    }

    const float t2A0 = t2s[R0 + g],      t2B0 = t2s[R0 + 8 + g];
    const float t2A1 = t2s[R0 + 16 + g], t2B1 = t2s[R0 + 24 + g];

    // ---- mainloop: S = G*X^T -> +bias, relu -> pack -> U += P*X (trans-LDSM) ----
    float4 ctx[2][8];
    #pragma unroll
    for (int mt = 0; mt < 2; mt++)
        #pragma unroll
        for (int nt = 0; nt < 8; nt++) ctx[mt][nt] = make_float4(0.f, 0.f, 0.f, 0.f);
    float den[2][2] = {{0.f, 0.f}, {0.f, 0.f}};

    #pragma unroll 2
    for (int cb = 0; cb < 16; cb++) {
        const float tc0 = t3s[16 * cb + 2 * t],     tc1 = t3s[16 * cb + 2 * t + 1];
        const float tc2 = t3s[16 * cb + 8 + 2 * t], tc3 = t3s[16 * cb + 8 + 2 * t + 1];
        float4 s[2][2];
        s[0][0] = make_float4(0.f, 0.f, 0.f, 0.f);
        s[0][1] = s[0][0]; s[1][0] = s[0][0]; s[1][1] = s[0][0];
        #pragma unroll
        for (int kt = 0; kt < 4; kt++) {
            unsigned q0, q1, q2, q3;
            ldsm4(q0, q1, q2, q3, &sX[(16 * cb + lro) * QS + 16 * kt + lco]);
            mma16(s[0][0], ga[0][kt], q0, q1);
            mma16(s[0][1], ga[0][kt], q2, q3);
            mma16(s[1][0], ga[1][kt], q0, q1);
            mma16(s[1][1], ga[1][kt], q2, q3);
        }
        unsigned pa[2][4];
        #pragma unroll
        for (int mt = 0; mt < 2; mt++) {
            const float tA = mt ? t2A1 : t2A0, tB = mt ? t2B1 : t2B0;
            float ex = fmaxf(s[mt][0].x + tA + tc0, 0.f), ey = fmaxf(s[mt][0].y + tA + tc1, 0.f);
            float ez = fmaxf(s[mt][0].z + tB + tc0, 0.f), ew = fmaxf(s[mt][0].w + tB + tc1, 0.f);
            float ox = fmaxf(s[mt][1].x + tA + tc2, 0.f), oy = fmaxf(s[mt][1].y + tA + tc3, 0.f);
            float oz = fmaxf(s[mt][1].z + tB + tc2, 0.f), ow = fmaxf(s[mt][1].w + tB + tc3, 0.f);
            den[mt][0] += (ex + ey) + (ox + oy);
            den[mt][1] += (ez + ew) + (oz + ow);
            pa[mt][0] = pack2(ex, ey); pa[mt][1] = pack2(ez, ew);
            pa[mt][2] = pack2(ox, oy); pa[mt][3] = pack2(oz, ow);
        }
        #pragma unroll
        for (int j = 0; j < 4; j++) {
            unsigned v0, v1, v2, v3;
            ldsm4t(v0, v1, v2, v3, &sX[(16 * cb + vro) * QS + 16 * j + vco]);
            mma16(ctx[0][2*j],   pa[0], v0, v1);
            mma16(ctx[0][2*j+1], pa[0], v2, v3);
            mma16(ctx[1][2*j],   pa[1], v0, v1);
            mma16(ctx[1][2*j+1], pa[1], v2, v3);
        }
    }

    // ---- normalize ----
    float inv[2][2], cden[2][2];
    #pragma unroll
    for (int mt = 0; mt < 2; mt++)
        #pragma unroll
        for (int hh = 0; hh < 2; hh++) {
            float d = den[mt][hh];
            d += __shfl_xor_sync(0xffffffffu, d, 1);
            d += __shfl_xor_sync(0xffffffffu, d, 2);
            inv[mt][hh]  = 1.0f / (d + 2.56e-10f);
            cden[mt][hh] = d * inv[mt][hh];
        }
    unsigned cf[2][4][4];
    #pragma unroll
    for (int mt = 0; mt < 2; mt++)
        #pragma unroll
        for (int kt = 0; kt < 4; kt++) {
            cf[mt][kt][0] = pack2(ctx[mt][2*kt].x * inv[mt][0],   ctx[mt][2*kt].y * inv[mt][0]);
            cf[mt][kt][1] = pack2(ctx[mt][2*kt].z * inv[mt][1],   ctx[mt][2*kt].w * inv[mt][1]);
            cf[mt][kt][2] = pack2(ctx[mt][2*kt+1].x * inv[mt][0], ctx[mt][2*kt+1].y * inv[mt][0]);
            cf[mt][kt][3] = pack2(ctx[mt][2*kt+1].z * inv[mt][1], ctx[mt][2*kt+1].w * inv[mt][1]);
        }

    // ---- Y = U' * W2^T ----
    float4 y[2][8];
    #pragma unroll
    for (int mt = 0; mt < 2; mt++)
        #pragma unroll
        for (int nt = 0; nt < 8; nt++) y[mt][nt] = make_float4(0.f, 0.f, 0.f, 0.f);
    #pragma unroll
    for (int kt = 0; kt < 4; kt++)
        #pragma unroll
        for (int j = 0; j < 4; j++) {
            unsigned b0, b1, b2, b3;
            ldsm4(b0, b1, b2, b3, &sW[(64 + 16 * j + lro) * WS + 16 * kt + lco]);
            mma16(y[0][2*j],   cf[0][kt], b0, b1);
            mma16(y[0][2*j+1], cf[0][kt], b2, b3);
            mma16(y[1][2*j],   cf[1][kt], b0, b1);
            mma16(y[1][2*j+1], cf[1][kt], b2, b3);
        }

    // ---- epilogue: + cden*wbv + bo + x, LayerNorm, store ----
    #pragma unroll
    for (int mt = 0; mt < 2; mt++) {
        const int rA = R0 + 16 * mt + g, rB = rA + 8;
        const float c0 = cden[mt][0], c1 = cden[mt][1];
        float s0 = 0.f, s1 = 0.f, q0 = 0.f, q1 = 0.f;
        #pragma unroll
        for (int nt = 0; nt < 8; nt++) {
            int c = 8 * nt + 2 * t;
            float2 wv = *(const float2*)&g_wbv[c];
            float2 bb = __ldg((const float2*)&bo[c]);
            float2 x0 = *(const float2*)&xg[rA * 64 + c];
            float2 x1 = *(const float2*)&xg[rB * 64 + c];
            y[mt][nt].x += c0 * wv.x + bb.x + x0.x;
            y[mt][nt].y += c0 * wv.y + bb.y + x0.y;
            y[mt][nt].z += c1 * wv.x + bb.x + x1.x;
            y[mt][nt].w += c1 * wv.y + bb.y + x1.y;
            s0 += y[mt][nt].x + y[mt][nt].y;  q0 += y[mt][nt].x * y[mt][nt].x + y[mt][nt].y * y[mt][nt].y;
            s1 += y[mt][nt].z + y[mt][nt].w;  q1 += y[mt][nt].z * y[mt][nt].z + y[mt][nt].w * y[mt][nt].w;
        }
        s0 += __shfl_xor_sync(0xffffffffu, s0, 1); s0 += __shfl_xor_sync(0xffffffffu, s0, 2);
        q0 += __shfl_xor_sync(0xffffffffu, q0, 1); q0 += __shfl_xor_sync(0xffffffffu, q0, 2);
        s1 += __shfl_xor_sync(0xffffffffu, s1, 1); s1 += __shfl_xor_sync(0xffffffffu, s1, 2);
        q1 += __shfl_xor_sync(0xffffffffu, q1, 1); q1 += __shfl_xor_sync(0xffffffffu, q1, 2);
        float mu0 = s0 * (1.f / 64.f), mu1 = s1 * (1.f / 64.f);
        float rs0 = rsqrtf(q0 * (1.f / 64.f) - mu0 * mu0 + 1e-5f);
        float rs1 = rsqrtf(q1 * (1.f / 64.f) - mu1 * mu1 + 1e-5f);
        #pragma unroll
        for (int nt = 0; nt < 8; nt++) {
            int c = 8 * nt + 2 * t;
            float2 gg = __ldg((const float2*)&lng[c]);
            float2 bb = __ldg((const float2*)&lnb[c]);
            *(float2*)&og[rA * 64 + c] = make_float2((y[mt][nt].x - mu0) * rs0 * gg.x + bb.x,
                                                     (y[mt][nt].y - mu0) * rs0 * gg.y + bb.y);
            *(float2*)&og[rB * 64 + c] = make_float2((y[mt][nt].z - mu1) * rs1 * gg.x + bb.x,
                                                     (y[mt][nt].w - mu1) * rs1 * gg.y + bb.y);
        }
    }
}

extern "C" void kernel_launch(void* const* d_in, const int* in_sizes, int n_in,
                              void* d_out, int out_size)
{
    const float* x   = (const float*)d_in[1];
    const float* Wq  = (const float*)d_in[2];
    const float* bq  = (const float*)d_in[3];
    const float* Wk  = (const float*)d_in[4];
    const float* bk  = (const float*)d_in[5];
    const float* Wv  = (const float*)d_in[6];
    const float* bv  = (const float*)d_in[7];
    const float* Wo  = (const float*)d_in[8];
    const float* bo  = (const float*)d_in[9];
    const float* lng = (const float*)d_in[10];
    const float* lnb = (const float*)d_in[11];
    float* out = (float*)d_out;

    int tiles = in_sizes[1] / (256 * 64);   // B*N = 1024

    precompute_kernel<<<2, 256>>>(Wq, Wk, Wv, Wo, bq, bk, bv);

    // smem: (256*QS + 2*64*WS) halves + 512 floats = 55296 + 2048 = 57344 B
    size_t smem = (size_t)(256 * QS + 2 * 64 * WS) * sizeof(__half) + 512 * sizeof(float);
    cudaFuncSetAttribute(pair_attn_v9,
                         cudaFuncAttributeMaxDynamicSharedMemorySize, (int)smem);

    pair_attn_v9<<<tiles, 256, smem>>>(x, bo, lng, lnb, out);
}

// round 14
// speedup vs baseline: 1.4155x; 1.1598x over previous
#include <cuda_runtime.h>
#include <cuda_fp16.h>

// B=4, N=256, M=256, D=64. One CTA per (b,i) tile; SINGLE kernel (no precompute launch).
// Algebra: Wg[n][k]=(Wk^T Wq)[k][n]/8 (in-CTA via MMA), W2[n][k]=(Wo Wv)[n][k] (MMA),
//   h1=Wk^T bq/8, h2=Wq^T bk/8 (scalar, rows 64/65 of Wg buffer), wbv=Wo bv, s0=bk.bq/8.
// G = X*Wg (+extra n-tile -> t2,t3 per row) ; S = G*X^T + t2_a + t3_c ; P = relu(S)
// U = P*X (trans-ldmatrix on sX) ; out = U*inv*W2^T + cden*wbv + bo + x ; LayerNorm.
// 256 threads = 8 warps; warp w owns rows [32w,32w+32).
// NOTE trans-ldmatrix lane maps: B-operand uses vro/vco; A-operand uses lro/lco
// (A-fragment reg1 is +8 in m, so pre-trans tile1 must be +8 in columns).

#define QS 72
#define WS 72
// smem half offsets
#define OX   0
#define OWQ  18432
#define OWK  23040
#define OWV  27648
#define OWO  32256
#define OWG  36864   // 80 rows: 0-63 Wg, 64 h1, 65 h2, 66-79 zero
#define OW2  42624
#define OEND 47232

__device__ __forceinline__ void mma16(float4& d, const unsigned a[4], unsigned b0, unsigned b1) {
    asm("mma.sync.aligned.m16n8k16.row.col.f32.f16.f16.f32 "
        "{%0,%1,%2,%3},{%4,%5,%6,%7},{%8,%9},{%0,%1,%2,%3};"
        : "+f"(d.x), "+f"(d.y), "+f"(d.z), "+f"(d.w)
        : "r"(a[0]), "r"(a[1]), "r"(a[2]), "r"(a[3]), "r"(b0), "r"(b1));
}
__device__ __forceinline__ void ldsm4(unsigned& r0, unsigned& r1, unsigned& r2, unsigned& r3,
                                      const __half* p) {
    unsigned a = (unsigned)__cvta_generic_to_shared(p);
    asm volatile("ldmatrix.sync.aligned.m8n8.x4.shared.b16 {%0,%1,%2,%3},[%4];"
                 : "=r"(r0), "=r"(r1), "=r"(r2), "=r"(r3) : "r"(a));
}
__device__ __forceinline__ void ldsm4t(unsigned& r0, unsigned& r1, unsigned& r2, unsigned& r3,
                                       const __half* p) {
    unsigned a = (unsigned)__cvta_generic_to_shared(p);
    asm volatile("ldmatrix.sync.aligned.m8n8.x4.trans.shared.b16 {%0,%1,%2,%3},[%4];"
                 : "=r"(r0), "=r"(r1), "=r"(r2), "=r"(r3) : "r"(a));
}
__device__ __forceinline__ unsigned pack2(float lo, float hi) {
    __half2 h = __floats2half2_rn(lo, hi);
    return *reinterpret_cast<unsigned*>(&h);
}
__device__ __forceinline__ void stageW(const float* __restrict__ W, __half* dst, int tid) {
    const int f  = tid >> 2;
    const int e0 = (tid & 3) * 16;
    const float* src = W + f * 64 + e0;
    unsigned u[8];
    #pragma unroll
    for (int i = 0; i < 4; i++) {
        float4 p = *(const float4*)(src + 4 * i);
        u[2*i]   = pack2(p.x, p.y);
        u[2*i+1] = pack2(p.z, p.w);
    }
    *(uint4*)&dst[f * WS + e0]     = *(uint4*)&u[0];
    *(uint4*)&dst[f * WS + e0 + 8] = *(uint4*)&u[4];
}

__global__ void __launch_bounds__(256, 1)
pair_attn_v11(const float* __restrict__ x_all,
              const float* __restrict__ Wq, const float* __restrict__ bq,
              const float* __restrict__ Wk, const float* __restrict__ bk,
              const float* __restrict__ Wv, const float* __restrict__ bv,
              const float* __restrict__ Wo, const float* __restrict__ bo,
              const float* __restrict__ lng, const float* __restrict__ lnb,
              float* __restrict__ out_all)
{
    extern __shared__ __half sm[];
    __half* sX  = sm + OX;
    __half* sWg = sm + OWG;
    __half* sW2 = sm + OW2;
    float*  fs   = (float*)(sm + OEND);
    float*  t3s  = fs;          // [256]
    float*  swbv = fs + 256;    // [64]
    float*  s0s  = fs + 320;    // [1]

    const int tid  = threadIdx.x;
    const int lane = tid & 31;
    const int wrp  = tid >> 5;
    const int g    = lane >> 2;
    const int t    = lane & 3;
    const int R0   = wrp * 32;
    const int lro  = ((lane >> 4) & 1) * 8 + (lane & 7);  // non-trans B map / trans A map
    const int lco  = ((lane >> 3) & 1) * 8;
    const int vro  = ((lane >> 3) & 1) * 8 + (lane & 7);  // trans B map
    const int vco  = ((lane >> 4) & 1) * 8;
    const int aro  = lane & 15;                           // non-trans A map
    const int aco  = ((lane >> 4) & 1) * 8;

    const float* xg = x_all   + (size_t)blockIdx.x * 16384;
    float*       og = out_all + (size_t)blockIdx.x * 16384;

    // ================= Phase A: staging =================
    {
        const float4* x4 = (const float4*)xg;
        #pragma unroll
        for (int i = 0; i < 16; i++) {
            int idx = tid + 256 * i;
            int row = idx >> 4, c4 = idx & 15;
            float4 v = x4[idx];
            *(uint2*)&sX[row * QS + c4 * 4] = make_uint2(pack2(v.x, v.y), pack2(v.z, v.w));
        }
        stageW(Wq, sm + OWQ, tid);
        stageW(Wk, sm + OWK, tid);
        stageW(Wv, sm + OWV, tid);
        stageW(Wo, sm + OWO, tid);
        // zero pad rows 66..79 of Wg buffer (14 rows * 36 words = 504)
        unsigned* wz = (unsigned*)(sWg + 66 * WS);
        for (int i = tid; i < 504; i += 256) wz[i] = 0;
        // h1, h2, wbv, s0
        if (tid < 64) {
            float a0 = 0.f, a1 = 0.f, a2 = 0.f, a3 = 0.f;
            for (int j = 0; j < 64; j += 4) {
                a0 = fmaf(__ldg(bq + j + 0), __ldg(Wk + (j + 0) * 64 + tid), a0);
                a1 = fmaf(__ldg(bq + j + 1), __ldg(Wk + (j + 1) * 64 + tid), a1);
                a2 = fmaf(__ldg(bq + j + 2), __ldg(Wk + (j + 2) * 64 + tid), a2);
                a3 = fmaf(__ldg(bq + j + 3), __ldg(Wk + (j + 3) * 64 + tid), a3);
            }
            sWg[64 * WS + tid] = __float2half_rn(((a0 + a1) + (a2 + a3)) * 0.125f);
        } else if (tid < 128) {
            int i = tid - 64;
            float a0 = 0.f, a1 = 0.f, a2 = 0.f, a3 = 0.f;
            for (int j = 0; j < 64; j += 4) {
                a0 = fmaf(__ldg(bk + j + 0), __ldg(Wq + (j + 0) * 64 + i), a0);
                a1 = fmaf(__ldg(bk + j + 1), __ldg(Wq + (j + 1) * 64 + i), a1);
                a2 = fmaf(__ldg(bk + j + 2), __ldg(Wq + (j + 2) * 64 + i), a2);
                a3 = fmaf(__ldg(bk + j + 3), __ldg(Wq + (j + 3) * 64 + i), a3);
            }
            sWg[65 * WS + i] = __float2half_rn(((a0 + a1) + (a2 + a3)) * 0.125f);
        } else if (tid < 192) {
            int i = tid - 128;
            float a = 0.f;
            for (int j = 0; j < 64; j += 4) {
                float4 w = __ldg((const float4*)&Wo[i * 64 + j]);
                float4 b = __ldg((const float4*)&bv[j]);
                a += w.x * b.x + w.y * b.y + w.z * b.z + w.w * b.w;
            }
            swbv[i] = a;
        } else if (tid == 192) {
            float s = 0.f;
            for (int j = 0; j < 64; j++) s = fmaf(__ldg(bk + j), __ldg(bq + j), s);
            s0s[0] = s * 0.125f;
        }
    }
    __syncthreads();   // B1

    // ================= Phase B: Wg / W2 via MMA =================
    if (wrp < 4) {
        // Wg[m][k'] = sum_j Wq[j][m] * Wk[j][k'] / 8  (A = Wq^T via trans-A map, B = Wk^T)
        const int m0 = 16 * wrp;
        float4 dW[8];
        #pragma unroll
        for (int nt = 0; nt < 8; nt++) dW[nt] = make_float4(0.f, 0.f, 0.f, 0.f);
        #pragma unroll
        for (int kt = 0; kt < 4; kt++) {
            unsigned a[4];
            // FIX: trans-A uses lro/lco (reg1 = +8 in m -> +8 pre-trans columns)
            ldsm4t(a[0], a[1], a[2], a[3], &sm[OWQ + (16 * kt + lro) * WS + m0 + lco]);
            #pragma unroll
            for (int jj = 0; jj < 4; jj++) {
                unsigned b0, b1, b2, b3;
                ldsm4t(b0, b1, b2, b3, &sm[OWK + (16 * kt + vro) * WS + 16 * jj + vco]);
                mma16(dW[2*jj],   a, b0, b1);
                mma16(dW[2*jj+1], a, b2, b3);
            }
        }
        #pragma unroll
        for (int nt = 0; nt < 8; nt++) {
            *(unsigned*)&sWg[(m0 + g) * WS + 8 * nt + 2 * t]     = pack2(dW[nt].x * 0.125f, dW[nt].y * 0.125f);
            *(unsigned*)&sWg[(m0 + 8 + g) * WS + 8 * nt + 2 * t] = pack2(dW[nt].z * 0.125f, dW[nt].w * 0.125f);
        }
    } else {
        // W2[m][k'] = sum_j Wo[m][j] * Wv[j][k']  (A = Wo non-trans, B = Wv^T)
        const int m0 = 16 * (wrp - 4);
        float4 dW[8];
        #pragma unroll
        for (int nt = 0; nt < 8; nt++) dW[nt] = make_float4(0.f, 0.f, 0.f, 0.f);
        #pragma unroll
        for (int kt = 0; kt < 4; kt++) {
            unsigned a[4];
            ldsm4(a[0], a[1], a[2], a[3], &sm[OWO + (m0 + aro) * WS + 16 * kt + aco]);
            #pragma unroll
            for (int jj = 0; jj < 4; jj++) {
                unsigned b0, b1, b2, b3;
                ldsm4t(b0, b1, b2, b3, &sm[OWV + (16 * kt + vro) * WS + 16 * jj + vco]);
                mma16(dW[2*jj],   a, b0, b1);
                mma16(dW[2*jj+1], a, b2, b3);
            }
        }
        #pragma unroll
        for (int nt = 0; nt < 8; nt++) {
            *(unsigned*)&sW2[(m0 + g) * WS + 8 * nt + 2 * t]     = pack2(dW[nt].x, dW[nt].y);
            *(unsigned*)&sW2[(m0 + 8 + g) * WS + 8 * nt + 2 * t] = pack2(dW[nt].z, dW[nt].w);
        }
    }
    __syncthreads();   // B2

    // ================= Phase C: G = X*Wg (+ t2/t3 extra tile) =================
    unsigned ga[2][4][4];
    float t2A0, t2B0, t2A1, t2B1;
    {
        unsigned xa[2][4][4];
        #pragma unroll
        for (int mt = 0; mt < 2; mt++)
            #pragma unroll
            for (int kt = 0; kt < 4; kt++)
                ldsm4(xa[mt][kt][0], xa[mt][kt][1], xa[mt][kt][2], xa[mt][kt][3],
                      &sX[(R0 + 16 * mt + aro) * QS + 16 * kt + aco]);
        float4 d0[8], d1[8], dE0, dE1;
        #pragma unroll
        for (int nt = 0; nt < 8; nt++) {
            d0[nt] = make_float4(0.f, 0.f, 0.f, 0.f);
            d1[nt] = d0[nt];
        }
        dE0 = make_float4(0.f, 0.f, 0.f, 0.f); dE1 = dE0;
        #pragma unroll
        for (int kt = 0; kt < 4; kt++) {
            #pragma unroll
            for (int j = 0; j < 4; j++) {
                unsigned b0, b1, b2, b3;
                ldsm4(b0, b1, b2, b3, &sWg[(16 * j + lro) * WS + 16 * kt + lco]);
                mma16(d0[2*j],   xa[0][kt], b0, b1);
                mma16(d0[2*j+1], xa[0][kt], b2, b3);
                mma16(d1[2*j],   xa[1][kt], b0, b1);
                mma16(d1[2*j+1], xa[1][kt], b2, b3);
            }
            unsigned e0, e1, e2, e3;
            ldsm4(e0, e1, e2, e3, &sWg[(64 + lro) * WS + 16 * kt + lco]);
            mma16(dE0, xa[0][kt], e0, e1);
            mma16(dE1, xa[1][kt], e0, e1);
        }
        #pragma unroll
        for (int kt = 0; kt < 4; kt++) {
            ga[0][kt][0] = pack2(d0[2*kt].x,   d0[2*kt].y);
            ga[0][kt][1] = pack2(d0[2*kt].z,   d0[2*kt].w);
            ga[0][kt][2] = pack2(d0[2*kt+1].x, d0[2*kt+1].y);
            ga[0][kt][3] = pack2(d0[2*kt+1].z, d0[2*kt+1].w);
            ga[1][kt][0] = pack2(d1[2*kt].x,   d1[2*kt].y);
            ga[1][kt][1] = pack2(d1[2*kt].z,   d1[2*kt].w);
            ga[1][kt][2] = pack2(d1[2*kt+1].x, d1[2*kt+1].y);
            ga[1][kt][3] = pack2(d1[2*kt+1].z, d1[2*kt+1].w);
        }
        // t2 (col 64) and t3 (col 65) live in lanes with t==0
        const float s0v = s0s[0];
        if (t == 0) {
            t3s[R0 + g]      = dE0.y + s0v;
            t3s[R0 + 8 + g]  = dE0.w + s0v;
            t3s[R0 + 16 + g] = dE1.y + s0v;
            t3s[R0 + 24 + g] = dE1.w + s0v;
        }
        t2A0 = __shfl_sync(0xffffffffu, dE0.x, lane & ~3);
        t2B0 = __shfl_sync(0xffffffffu, dE0.z, lane & ~3);
        t2A1 = __shfl_sync(0xffffffffu, dE1.x, lane & ~3);
        t2B1 = __shfl_sync(0xffffffffu, dE1.z, lane & ~3);
    }
    __syncthreads();   // B3 (t3s visible)

    // ================= Mainloop =================
    float4 ctx[2][8];
    #pragma unroll
    for (int mt = 0; mt < 2; mt++)
        #pragma unroll
        for (int nt = 0; nt < 8; nt++) ctx[mt][nt] = make_float4(0.f, 0.f, 0.f, 0.f);
    float den[2][2] = {{0.f, 0.f}, {0.f, 0.f}};

    #pragma unroll 2
    for (int cb = 0; cb < 16; cb++) {
        const float2 tcA = *(const float2*)&t3s[16 * cb + 2 * t];
        const float2 tcB = *(const float2*)&t3s[16 * cb + 8 + 2 * t];
        float4 s[2][2];
        s[0][0] = make_float4(0.f, 0.f, 0.f, 0.f);
        s[0][1] = s[0][0]; s[1][0] = s[0][0]; s[1][1] = s[0][0];
        #pragma unroll
        for (int kt = 0; kt < 4; kt++) {
            unsigned q0, q1, q2, q3;
            ldsm4(q0, q1, q2, q3, &sX[(16 * cb + lro) * QS + 16 * kt + lco]);
            mma16(s[0][0], ga[0][kt], q0, q1);
            mma16(s[0][1], ga[0][kt], q2, q3);
            mma16(s[1][0], ga[1][kt], q0, q1);
            mma16(s[1][1], ga[1][kt], q2, q3);
        }
        unsigned pa[2][4];
        #pragma unroll
        for (int mt = 0; mt < 2; mt++) {
            const float tA = mt ? t2A1 : t2A0, tB = mt ? t2B1 : t2B0;
            float ex = fmaxf(s[mt][0].x + tA + tcA.x, 0.f), ey = fmaxf(s[mt][0].y + tA + tcA.y, 0.f);
            float ez = fmaxf(s[mt][0].z + tB + tcA.x, 0.f), ew = fmaxf(s[mt][0].w + tB + tcA.y, 0.f);
            float ox = fmaxf(s[mt][1].x + tA + tcB.x, 0.f), oy = fmaxf(s[mt][1].y + tA + tcB.y, 0.f);
            float oz = fmaxf(s[mt][1].z + tB + tcB.x, 0.f), ow = fmaxf(s[mt][1].w + tB + tcB.y, 0.f);
            den[mt][0] += (ex + ey) + (ox + oy);
            den[mt][1] += (ez + ew) + (oz + ow);
            pa[mt][0] = pack2(ex, ey); pa[mt][1] = pack2(ez, ew);
            pa[mt][2] = pack2(ox, oy); pa[mt][3] = pack2(oz, ow);
        }
        #pragma unroll
        for (int j = 0; j < 4; j++) {
            unsigned v0, v1, v2, v3;
            ldsm4t(v0, v1, v2, v3, &sX[(16 * cb + vro) * QS + 16 * j + vco]);
            mma16(ctx[0][2*j],   pa[0], v0, v1);
            mma16(ctx[0][2*j+1], pa[0], v2, v3);
            mma16(ctx[1][2*j],   pa[1], v0, v1);
            mma16(ctx[1][2*j+1], pa[1], v2, v3);
        }
    }

    // ================= Normalize =================
    float inv[2][2], cden[2][2];
    #pragma unroll
    for (int mt = 0; mt < 2; mt++)
        #pragma unroll
        for (int hh = 0; hh < 2; hh++) {
            float d = den[mt][hh];
            d += __shfl_xor_sync(0xffffffffu, d, 1);
            d += __shfl_xor_sync(0xffffffffu, d, 2);
            inv[mt][hh]  = 1.0f / (d + 2.56e-10f);
            cden[mt][hh] = d * inv[mt][hh];
        }
    unsigned cf[2][4][4];
    #pragma unroll
    for (int mt = 0; mt < 2; mt++)
        #pragma unroll
        for (int kt = 0; kt < 4; kt++) {
            cf[mt][kt][0] = pack2(ctx[mt][2*kt].x * inv[mt][0],   ctx[mt][2*kt].y * inv[mt][0]);
            cf[mt][kt][1] = pack2(ctx[mt][2*kt].z * inv[mt][1],   ctx[mt][2*kt].w * inv[mt][1]);
            cf[mt][kt][2] = pack2(ctx[mt][2*kt+1].x * inv[mt][0], ctx[mt][2*kt+1].y * inv[mt][0]);
            cf[mt][kt][3] = pack2(ctx[mt][2*kt+1].z * inv[mt][1], ctx[mt][2*kt+1].w * inv[mt][1]);
        }

    // ================= Y = U' * W2^T =================
    float4 y[2][8];
    #pragma unroll
    for (int mt = 0; mt < 2; mt++)
        #pragma unroll
        for (int nt = 0; nt < 8; nt++) y[mt][nt] = make_float4(0.f, 0.f, 0.f, 0.f);
    #pragma unroll
    for (int kt = 0; kt < 4; kt++)
        #pragma unroll
        for (int j = 0; j < 4; j++) {
            unsigned b0, b1, b2, b3;
            ldsm4(b0, b1, b2, b3, &sW2[(16 * j + lro) * WS + 16 * kt + lco]);
            mma16(y[0][2*j],   cf[0][kt], b0, b1);
            mma16(y[0][2*j+1], cf[0][kt], b2, b3);
            mma16(y[1][2*j],   cf[1][kt], b0, b1);
            mma16(y[1][2*j+1], cf[1][kt], b2, b3);
        }

    // ================= Epilogue =================
    #pragma unroll
    for (int mt = 0; mt < 2; mt++) {
        const int rA = R0 + 16 * mt + g, rB = rA + 8;
        const float c0 = cden[mt][0], c1 = cden[mt][1];
        float s0 = 0.f, s1 = 0.f, q0 = 0.f, q1 = 0.f;
        #pragma unroll
        for (int nt = 0; nt < 8; nt++) {
            int c = 8 * nt + 2 * t;
            float2 wv = *(const float2*)&swbv[c];
            float2 bb = __ldg((const float2*)&bo[c]);
            float2 x0 = *(const float2*)&xg[rA * 64 + c];
            float2 x1 = *(const float2*)&xg[rB * 64 + c];
            y[mt][nt].x += c0 * wv.x + bb.x + x0.x;
            y[mt][nt].y += c0 * wv.y + bb.y + x0.y;
            y[mt][nt].z += c1 * wv.x + bb.x + x1.x;
            y[mt][nt].w += c1 * wv.y + bb.y + x1.y;
            s0 += y[mt][nt].x + y[mt][nt].y;  q0 += y[mt][nt].x * y[mt][nt].x + y[mt][nt].y * y[mt][nt].y;
            s1 += y[mt][nt].z + y[mt][nt].w;  q1 += y[mt][nt].z * y[mt][nt].z + y[mt][nt].w * y[mt][nt].w;
        }
        s0 += __shfl_xor_sync(0xffffffffu, s0, 1); s0 += __shfl_xor_sync(0xffffffffu, s0, 2);
        q0 += __shfl_xor_sync(0xffffffffu, q0, 1); q0 += __shfl_xor_sync(0xffffffffu, q0, 2);
        s1 += __shfl_xor_sync(0xffffffffu, s1, 1); s1 += __shfl_xor_sync(0xffffffffu, s1, 2);
        q1 += __shfl_xor_sync(0xffffffffu, q1, 1); q1 += __shfl_xor_sync(0xffffffffu, q1, 2);
        float mu0 = s0 * (1.f / 64.f), mu1 = s1 * (1.f / 64.f);
        float rs0 = rsqrtf(q0 * (1.f / 64.f) - mu0 * mu0 + 1e-5f);
        float rs1 = rsqrtf(q1 * (1.f / 64.f) - mu1 * mu1 + 1e-5f);
        #pragma unroll
        for (int nt = 0; nt < 8; nt++) {
            int c = 8 * nt + 2 * t;
            float2 gg = __ldg((const float2*)&lng[c]);
            float2 bb = __ldg((const float2*)&lnb[c]);
            *(float2*)&og[rA * 64 + c] = make_float2((y[mt][nt].x - mu0) * rs0 * gg.x + bb.x,
                                                     (y[mt][nt].y - mu0) * rs0 * gg.y + bb.y);
            *(float2*)&og[rB * 64 + c] = make_float2((y[mt][nt].z - mu1) * rs1 * gg.x + bb.x,
                                                     (y[mt][nt].w - mu1) * rs1 * gg.y + bb.y);
        }
    }
}

extern "C" void kernel_launch(void* const* d_in, const int* in_sizes, int n_in,
                              void* d_out, int out_size)
{
    const float* x   = (const float*)d_in[1];
    const float* Wq  = (const float*)d_in[2];
    const float* bq  = (const float*)d_in[3];
    const float* Wk  = (const float*)d_in[4];
    const float* bk  = (const float*)d_in[5];
    const float* Wv  = (const float*)d_in[6];
    const float* bv  = (const float*)d_in[7];
    const float* Wo  = (const float*)d_in[8];
    const float* bo  = (const float*)d_in[9];
    const float* lng = (const float*)d_in[10];
    const float* lnb = (const float*)d_in[11];
    float* out = (float*)d_out;

    int tiles = in_sizes[1] / (256 * 64);   // B*N = 1024

    size_t smem = (size_t)OEND * sizeof(__half) + 321 * sizeof(float) + 12;
    cudaFuncSetAttribute(pair_attn_v11,
                         cudaFuncAttributeMaxDynamicSharedMemorySize, (int)smem);

    pair_attn_v11<<<tiles, 256, smem>>>(x, Wq, bq, Wk, bk, Wv, bv, Wo, bo,
                                        lng, lnb, out);
}

// round 15
// speedup vs baseline: 1.4322x; 1.0118x over previous
#include <cuda_runtime.h>
#include <cuda_fp16.h>

// B=4, N=256, M=256, D=64. One CTA per (b,i) tile; SINGLE kernel.
// 512 threads = 16 warps (4 per SMSP for latency hiding); warp w owns rows [16w,16w+16).
// Fused algebra (in-CTA): Wg[n][k]=(Wk^T Wq)[k][n]/8, W2[n][k]=(Wo Wv)[n][k],
//   h1=Wk^T bq/8 (Wg row 64), h2=Wq^T bk/8 (row 65), wbv=Wo bv, s0=bk.bq/8.
// G = X*Wg (+extra n-tile -> t2,t3) ; S = G*X^T + t2_a + t3_c ; P = relu(S)
// U = P*X (trans-ldmatrix on sX) ; out = U*inv*W2^T + cden*wbv + bo + x ; LayerNorm.
// Lane maps: non-trans B = lro/lco ; trans B = vro/vco ; trans A = lro/lco ; non-trans A = aro/aco.

#define QS 72
#define WS 72
#define OX   0
#define OWQ  18432
#define OWK  23040
#define OWV  27648
#define OWO  32256
#define OWG  36864   // 80 rows: 0-63 Wg, 64 h1, 65 h2, 66-79 zero
#define OW2  42624
#define OEND 47232

__device__ __forceinline__ void mma16(float4& d, const unsigned a[4], unsigned b0, unsigned b1) {
    asm("mma.sync.aligned.m16n8k16.row.col.f32.f16.f16.f32 "
        "{%0,%1,%2,%3},{%4,%5,%6,%7},{%8,%9},{%0,%1,%2,%3};"
        : "+f"(d.x), "+f"(d.y), "+f"(d.z), "+f"(d.w)
        : "r"(a[0]), "r"(a[1]), "r"(a[2]), "r"(a[3]), "r"(b0), "r"(b1));
}
__device__ __forceinline__ void ldsm4(unsigned& r0, unsigned& r1, unsigned& r2, unsigned& r3,
                                      const __half* p) {
    unsigned a = (unsigned)__cvta_generic_to_shared(p);
    asm volatile("ldmatrix.sync.aligned.m8n8.x4.shared.b16 {%0,%1,%2,%3},[%4];"
                 : "=r"(r0), "=r"(r1), "=r"(r2), "=r"(r3) : "r"(a));
}
__device__ __forceinline__ void ldsm4t(unsigned& r0, unsigned& r1, unsigned& r2, unsigned& r3,
                                       const __half* p) {
    unsigned a = (unsigned)__cvta_generic_to_shared(p);
    asm volatile("ldmatrix.sync.aligned.m8n8.x4.trans.shared.b16 {%0,%1,%2,%3},[%4];"
                 : "=r"(r0), "=r"(r1), "=r"(r2), "=r"(r3) : "r"(a));
}
__device__ __forceinline__ unsigned pack2(float lo, float hi) {
    __half2 h = __floats2half2_rn(lo, hi);
    return *reinterpret_cast<unsigned*>(&h);
}
// 512-thread weight stage: thread -> row tid/8, 8-col run.
__device__ __forceinline__ void stageW512(const float* __restrict__ W, __half* dst, int tid) {
    const int f  = tid >> 3;
    const int e0 = (tid & 7) * 8;
    float4 p0 = *(const float4*)(W + f * 64 + e0);
    float4 p1 = *(const float4*)(W + f * 64 + e0 + 4);
    unsigned u[4] = {pack2(p0.x, p0.y), pack2(p0.z, p0.w),
                     pack2(p1.x, p1.y), pack2(p1.z, p1.w)};
    *(uint4*)&dst[f * WS + e0] = *(uint4*)u;
}

__global__ void __launch_bounds__(512, 1)
pair_attn_v12(const float* __restrict__ x_all,
              const float* __restrict__ Wq, const float* __restrict__ bq,
              const float* __restrict__ Wk, const float* __restrict__ bk,
              const float* __restrict__ Wv, const float* __restrict__ bv,
              const float* __restrict__ Wo, const float* __restrict__ bo,
              const float* __restrict__ lng, const float* __restrict__ lnb,
              float* __restrict__ out_all)
{
    extern __shared__ __half sm[];
    __half* sX  = sm + OX;
    __half* sWg = sm + OWG;
    __half* sW2 = sm + OW2;
    float*  fs   = (float*)(sm + OEND);
    float*  t3s  = fs;          // [256]
    float*  swbv = fs + 256;    // [64]
    float*  s0s  = fs + 320;    // [1]

    const int tid  = threadIdx.x;
    const int lane = tid & 31;
    const int wrp  = tid >> 5;          // 0..15
    const int g    = lane >> 2;
    const int t    = lane & 3;
    const int R0   = wrp * 16;
    const int lro  = ((lane >> 4) & 1) * 8 + (lane & 7);  // non-trans B / trans A
    const int lco  = ((lane >> 3) & 1) * 8;
    const int vro  = ((lane >> 3) & 1) * 8 + (lane & 7);  // trans B
    const int vco  = ((lane >> 4) & 1) * 8;
    const int aro  = lane & 15;                           // non-trans A
    const int aco  = ((lane >> 4) & 1) * 8;

    const float* xg = x_all   + (size_t)blockIdx.x * 16384;
    float*       og = out_all + (size_t)blockIdx.x * 16384;

    // ================= Phase A: staging =================
    {
        const float4* x4 = (const float4*)xg;
        #pragma unroll
        for (int i = 0; i < 8; i++) {
            int idx = tid + 512 * i;
            int row = idx >> 4, c4 = idx & 15;
            float4 v = x4[idx];
            *(uint2*)&sX[row * QS + c4 * 4] = make_uint2(pack2(v.x, v.y), pack2(v.z, v.w));
        }
        stageW512(Wq, sm + OWQ, tid);
        stageW512(Wk, sm + OWK, tid);
        stageW512(Wv, sm + OWV, tid);
        stageW512(Wo, sm + OWO, tid);
        unsigned* wz = (unsigned*)(sWg + 66 * WS);
        for (int i = tid; i < 504; i += 512) wz[i] = 0;
        if (tid < 64) {
            float a0 = 0.f, a1 = 0.f, a2 = 0.f, a3 = 0.f;
            #pragma unroll
            for (int j = 0; j < 64; j += 4) {
                a0 = fmaf(__ldg(bq + j + 0), __ldg(Wk + (j + 0) * 64 + tid), a0);
                a1 = fmaf(__ldg(bq + j + 1), __ldg(Wk + (j + 1) * 64 + tid), a1);
                a2 = fmaf(__ldg(bq + j + 2), __ldg(Wk + (j + 2) * 64 + tid), a2);
                a3 = fmaf(__ldg(bq + j + 3), __ldg(Wk + (j + 3) * 64 + tid), a3);
            }
            sWg[64 * WS + tid] = __float2half_rn(((a0 + a1) + (a2 + a3)) * 0.125f);
        } else if (tid < 128) {
            int i = tid - 64;
            float a0 = 0.f, a1 = 0.f, a2 = 0.f, a3 = 0.f;
            #pragma unroll
            for (int j = 0; j < 64; j += 4) {
                a0 = fmaf(__ldg(bk + j + 0), __ldg(Wq + (j + 0) * 64 + i), a0);
                a1 = fmaf(__ldg(bk + j + 1), __ldg(Wq + (j + 1) * 64 + i), a1);
                a2 = fmaf(__ldg(bk + j + 2), __ldg(Wq + (j + 2) * 64 + i), a2);
                a3 = fmaf(__ldg(bk + j + 3), __ldg(Wq + (j + 3) * 64 + i), a3);
            }
            sWg[65 * WS + i] = __float2half_rn(((a0 + a1) + (a2 + a3)) * 0.125f);
        } else if (tid < 192) {
            int i = tid - 128;
            float a = 0.f;
            #pragma unroll
            for (int j = 0; j < 64; j += 4) {
                float4 w = __ldg((const float4*)&Wo[i * 64 + j]);
                float4 b = __ldg((const float4*)&bv[j]);
                a += w.x * b.x + w.y * b.y + w.z * b.z + w.w * b.w;
            }
            swbv[i] = a;
        } else if (tid == 192) {
            float s = 0.f;
            #pragma unroll
            for (int j = 0; j < 64; j++) s = fmaf(__ldg(bk + j), __ldg(bq + j), s);
            s0s[0] = s * 0.125f;
        }
    }
    __syncthreads();   // B1

    // ================= Phase B: Wg / W2 via MMA (warps 0-7) =================
    if (wrp < 4) {
        const int m0 = 16 * wrp;
        float4 dW[8];
        #pragma unroll
        for (int nt = 0; nt < 8; nt++) dW[nt] = make_float4(0.f, 0.f, 0.f, 0.f);
        #pragma unroll
        for (int kt = 0; kt < 4; kt++) {
            unsigned a[4];
            ldsm4t(a[0], a[1], a[2], a[3], &sm[OWQ + (16 * kt + lro) * WS + m0 + lco]);
            #pragma unroll
            for (int jj = 0; jj < 4; jj++) {
                unsigned b0, b1, b2, b3;
                ldsm4t(b0, b1, b2, b3, &sm[OWK + (16 * kt + vro) * WS + 16 * jj + vco]);
                mma16(dW[2*jj],   a, b0, b1);
                mma16(dW[2*jj+1], a, b2, b3);
            }
        }
        #pragma unroll
        for (int nt = 0; nt < 8; nt++) {
            *(unsigned*)&sWg[(m0 + g) * WS + 8 * nt + 2 * t]     = pack2(dW[nt].x * 0.125f, dW[nt].y * 0.125f);
            *(unsigned*)&sWg[(m0 + 8 + g) * WS + 8 * nt + 2 * t] = pack2(dW[nt].z * 0.125f, dW[nt].w * 0.125f);
        }
    } else if (wrp < 8) {
        const int m0 = 16 * (wrp - 4);
        float4 dW[8];
        #pragma unroll
        for (int nt = 0; nt < 8; nt++) dW[nt] = make_float4(0.f, 0.f, 0.f, 0.f);
        #pragma unroll
        for (int kt = 0; kt < 4; kt++) {
            unsigned a[4];
            ldsm4(a[0], a[1], a[2], a[3], &sm[OWO + (m0 + aro) * WS + 16 * kt + aco]);
            #pragma unroll
            for (int jj = 0; jj < 4; jj++) {
                unsigned b0, b1, b2, b3;
                ldsm4t(b0, b1, b2, b3, &sm[OWV + (16 * kt + vro) * WS + 16 * jj + vco]);
                mma16(dW[2*jj],   a, b0, b1);
                mma16(dW[2*jj+1], a, b2, b3);
            }
        }
        #pragma unroll
        for (int nt = 0; nt < 8; nt++) {
            *(unsigned*)&sW2[(m0 + g) * WS + 8 * nt + 2 * t]     = pack2(dW[nt].x, dW[nt].y);
            *(unsigned*)&sW2[(m0 + 8 + g) * WS + 8 * nt + 2 * t] = pack2(dW[nt].z, dW[nt].w);
        }
    }
    __syncthreads();   // B2

    // ================= Phase C: G = X*Wg (+t2/t3 tile) =================
    unsigned ga[4][4];
    float t2A, t2B;
    {
        unsigned xa[4][4];
        #pragma unroll
        for (int kt = 0; kt < 4; kt++)
            ldsm4(xa[kt][0], xa[kt][1], xa[kt][2], xa[kt][3],
                  &sX[(R0 + aro) * QS + 16 * kt + aco]);
        float4 d[8], dE;
        #pragma unroll
        for (int nt = 0; nt < 8; nt++) d[nt] = make_float4(0.f, 0.f, 0.f, 0.f);
        dE = make_float4(0.f, 0.f, 0.f, 0.f);
        #pragma unroll
        for (int kt = 0; kt < 4; kt++) {
            #pragma unroll
            for (int j = 0; j < 4; j++) {
                unsigned b0, b1, b2, b3;
                ldsm4(b0, b1, b2, b3, &sWg[(16 * j + lro) * WS + 16 * kt + lco]);
                mma16(d[2*j],   xa[kt], b0, b1);
                mma16(d[2*j+1], xa[kt], b2, b3);
            }
            unsigned e0, e1, e2, e3;
            ldsm4(e0, e1, e2, e3, &sWg[(64 + lro) * WS + 16 * kt + lco]);
            mma16(dE, xa[kt], e0, e1);
        }
        #pragma unroll
        for (int kt = 0; kt < 4; kt++) {
            ga[kt][0] = pack2(d[2*kt].x,   d[2*kt].y);
            ga[kt][1] = pack2(d[2*kt].z,   d[2*kt].w);
            ga[kt][2] = pack2(d[2*kt+1].x, d[2*kt+1].y);
            ga[kt][3] = pack2(d[2*kt+1].z, d[2*kt+1].w);
        }
        const float s0v = s0s[0];
        if (t == 0) {
            t3s[R0 + g]     = dE.y + s0v;
            t3s[R0 + 8 + g] = dE.w + s0v;
        }
        t2A = __shfl_sync(0xffffffffu, dE.x, lane & ~3);
        t2B = __shfl_sync(0xffffffffu, dE.z, lane & ~3);
    }
    __syncthreads();   // B3

    // ================= Mainloop =================
    float4 ctx[8];
    #pragma unroll
    for (int nt = 0; nt < 8; nt++) ctx[nt] = make_float4(0.f, 0.f, 0.f, 0.f);
    float den0 = 0.f, den1 = 0.f;

    #pragma unroll 2
    for (int cb = 0; cb < 16; cb++) {
        const float2 tcA = *(const float2*)&t3s[16 * cb + 2 * t];
        const float2 tcB = *(const float2*)&t3s[16 * cb + 8 + 2 * t];
        float4 s0 = make_float4(0.f, 0.f, 0.f, 0.f), s1 = s0;
        #pragma unroll
        for (int kt = 0; kt < 4; kt++) {
            unsigned q0, q1, q2, q3;
            ldsm4(q0, q1, q2, q3, &sX[(16 * cb + lro) * QS + 16 * kt + lco]);
            mma16(s0, ga[kt], q0, q1);
            mma16(s1, ga[kt], q2, q3);
        }
        float ex = fmaxf(s0.x + t2A + tcA.x, 0.f), ey = fmaxf(s0.y + t2A + tcA.y, 0.f);
        float ez = fmaxf(s0.z + t2B + tcA.x, 0.f), ew = fmaxf(s0.w + t2B + tcA.y, 0.f);
        float ox = fmaxf(s1.x + t2A + tcB.x, 0.f), oy = fmaxf(s1.y + t2A + tcB.y, 0.f);
        float oz = fmaxf(s1.z + t2B + tcB.x, 0.f), ow = fmaxf(s1.w + t2B + tcB.y, 0.f);
        den0 += (ex + ey) + (ox + oy);
        den1 += (ez + ew) + (oz + ow);
        unsigned pa[4];
        pa[0] = pack2(ex, ey); pa[1] = pack2(ez, ew);
        pa[2] = pack2(ox, oy); pa[3] = pack2(oz, ow);
        #pragma unroll
        for (int j = 0; j < 4; j++) {
            unsigned v0, v1, v2, v3;
            ldsm4t(v0, v1, v2, v3, &sX[(16 * cb + vro) * QS + 16 * j + vco]);
            mma16(ctx[2*j],   pa, v0, v1);
            mma16(ctx[2*j+1], pa, v2, v3);
        }
    }

    // ================= Normalize =================
    den0 += __shfl_xor_sync(0xffffffffu, den0, 1);
    den0 += __shfl_xor_sync(0xffffffffu, den0, 2);
    den1 += __shfl_xor_sync(0xffffffffu, den1, 1);
    den1 += __shfl_xor_sync(0xffffffffu, den1, 2);
    const float inv0 = 1.0f / (den0 + 2.56e-10f), inv1 = 1.0f / (den1 + 2.56e-10f);
    const float cd0 = den0 * inv0, cd1 = den1 * inv1;
    unsigned cf[4][4];
    #pragma unroll
    for (int kt = 0; kt < 4; kt++) {
        cf[kt][0] = pack2(ctx[2*kt].x * inv0,   ctx[2*kt].y * inv0);
        cf[kt][1] = pack2(ctx[2*kt].z * inv1,   ctx[2*kt].w * inv1);
        cf[kt][2] = pack2(ctx[2*kt+1].x * inv0, ctx[2*kt+1].y * inv0);
        cf[kt][3] = pack2(ctx[2*kt+1].z * inv1, ctx[2*kt+1].w * inv1);
    }

    // ================= Y = U' * W2^T =================
    float4 y[8];
    #pragma unroll
    for (int nt = 0; nt < 8; nt++) y[nt] = make_float4(0.f, 0.f, 0.f, 0.f);
    #pragma unroll
    for (int kt = 0; kt < 4; kt++)
        #pragma unroll
        for (int j = 0; j < 4; j++) {
            unsigned b0, b1, b2, b3;
            ldsm4(b0, b1, b2, b3, &sW2[(16 * j + lro) * WS + 16 * kt + lco]);
            mma16(y[2*j],   cf[kt], b0, b1);
            mma16(y[2*j+1], cf[kt], b2, b3);
        }

    // ================= Epilogue =================
    {
        const int rA = R0 + g, rB = rA + 8;
        float s0 = 0.f, s1 = 0.f, q0 = 0.f, q1 = 0.f;
        #pragma unroll
        for (int nt = 0; nt < 8; nt++) {
            int c = 8 * nt + 2 * t;
            float2 wv = *(const float2*)&swbv[c];
            float2 bb = __ldg((const float2*)&bo[c]);
            float2 x0 = *(const float2*)&xg[rA * 64 + c];
            float2 x1 = *(const float2*)&xg[rB * 64 + c];
            y[nt].x += cd0 * wv.x + bb.x + x0.x;
            y[nt].y += cd0 * wv.y + bb.y + x0.y;
            y[nt].z += cd1 * wv.x + bb.x + x1.x;
            y[nt].w += cd1 * wv.y + bb.y + x1.y;
            s0 += y[nt].x + y[nt].y;  q0 += y[nt].x * y[nt].x + y[nt].y * y[nt].y;
            s1 += y[nt].z + y[nt].w;  q1 += y[nt].z * y[nt].z + y[nt].w * y[nt].w;
        }
        s0 += __shfl_xor_sync(0xffffffffu, s0, 1); s0 += __shfl_xor_sync(0xffffffffu, s0, 2);
        q0 += __shfl_xor_sync(0xffffffffu, q0, 1); q0 += __shfl_xor_sync(0xffffffffu, q0, 2);
        s1 += __shfl_xor_sync(0xffffffffu, s1, 1); s1 += __shfl_xor_sync(0xffffffffu, s1, 2);
        q1 += __shfl_xor_sync(0xffffffffu, q1, 1); q1 += __shfl_xor_sync(0xffffffffu, q1, 2);
        float mu0 = s0 * (1.f / 64.f), mu1 = s1 * (1.f / 64.f);
        float rs0 = rsqrtf(q0 * (1.f / 64.f) - mu0 * mu0 + 1e-5f);
        float rs1 = rsqrtf(q1 * (1.f / 64.f) - mu1 * mu1 + 1e-5f);
        #pragma unroll
        for (int nt = 0; nt < 8; nt++) {
            int c = 8 * nt + 2 * t;
            float2 gg = __ldg((const float2*)&lng[c]);
            float2 bb = __ldg((const float2*)&lnb[c]);
            *(float2*)&og[rA * 64 + c] = make_float2((y[nt].x - mu0) * rs0 * gg.x + bb.x,
                                                     (y[nt].y - mu0) * rs0 * gg.y + bb.y);
            *(float2*)&og[rB * 64 + c] = make_float2((y[nt].z - mu1) * rs1 * gg.x + bb.x,
                                                     (y[nt].w - mu1) * rs1 * gg.y + bb.y);
        }
    }
}

extern "C" void kernel_launch(void* const* d_in, const int* in_sizes, int n_in,
                              void* d_out, int out_size)
{
    const float* x   = (const float*)d_in[1];
    const float* Wq  = (const float*)d_in[2];
    const float* bq  = (const float*)d_in[3];
    const float* Wk  = (const float*)d_in[4];
    const float* bk  = (const float*)d_in[5];
    const float* Wv  = (const float*)d_in[6];
    const float* bv  = (const float*)d_in[7];
    const float* Wo  = (const float*)d_in[8];
    const float* bo  = (const float*)d_in[9];
    const float* lng = (const float*)d_in[10];
    const float* lnb = (const float*)d_in[11];
    float* out = (float*)d_out;

    int tiles = in_sizes[1] / (256 * 64);   // B*N = 1024

    size_t smem = (size_t)OEND * sizeof(__half) + 321 * sizeof(float) + 12;
    cudaFuncSetAttribute(pair_attn_v12,
                         cudaFuncAttributeMaxDynamicSharedMemorySize, (int)smem);

    pair_attn_v12<<<tiles, 512, smem>>>(x, Wq, bq, Wk, bk, Wv, bv, Wo, bo,
                                        lng, lnb, out);
}